// round 13
// baseline (speedup 1.0000x reference)
#include <cuda_runtime.h>
#include <cuda_fp16.h>
#include <math.h>
#include <cstdint>

#define NN 50000
#define EE 800000
#define BB 50
#define GN_EPS 1e-5f
#define MPAD 50048   // 391 * 128
#define SCAN_BLK 49  // ceil(NN / 1024)
#define GN_CHK 8

// ---------------- scratch (static device memory; no allocations) ----------------
__device__ __half g_abf[(size_t)MPAD * 1536];   // fp16 A; pad rows read-only garbage (discarded)
__device__ __half g_hbf[(size_t)NN * 512];      // fp16 GEMM output / final h
__device__ __half g_wbf[(size_t)512 * 2304];    // fp16 W (n-major)
__device__ __half g_cbf[(size_t)NN * 768];      // fp16 [P0|P1|P2] (mode B)
__device__ __half g_ubf[(size_t)NN * 256];      // fp16 u (mode B)
__device__ float g_s1[BB * 512];
__device__ float g_s2[BB * 512];
__device__ int   g_deg[NN];
__device__ float g_dinv[NN];
__device__ int   g_off[NN + 1];
__device__ int   g_fill[NN];
__device__ int   g_bsum[SCAN_BLK];
__device__ int   g_boff[SCAN_BLK];
__device__ int2  g_srcw[EE];   // {src, float_bits(w)}
__device__ int   g_ptr[BB + 1];
__device__ float g_cnt[BB];
__device__ float g_pool[BB * 128];

static inline int cdiv(int a, int b) { return (a + b - 1) / b; }

// ---------------- PTX helpers ----------------
__device__ __forceinline__ uint32_t smem_u32(const void* p) {
    uint32_t a;
    asm("{ .reg .u64 t; cvta.to.shared.u64 t, %1; cvt.u32.u64 %0, t; }" : "=r"(a) : "l"(p));
    return a;
}

__device__ __forceinline__ void cp_async16(uint32_t dst, const void* src) {
    asm volatile("cp.async.cg.shared.global [%0], [%1], 16;\n" :: "r"(dst), "l"(src));
}
#define CP_COMMIT() asm volatile("cp.async.commit_group;\n" ::: "memory")
#define CP_WAIT(n)  asm volatile("cp.async.wait_group %0;\n" :: "n"(n) : "memory")

__device__ __forceinline__ void mma_f16(float* c, uint32_t a0, uint32_t a1, uint32_t a2,
                                        uint32_t a3, uint32_t b0, uint32_t b1) {
    asm volatile(
        "mma.sync.aligned.m16n8k16.row.col.f32.f16.f16.f32 "
        "{%0,%1,%2,%3}, {%4,%5,%6,%7}, {%8,%9}, {%0,%1,%2,%3};"
        : "+f"(c[0]), "+f"(c[1]), "+f"(c[2]), "+f"(c[3])
        : "r"(a0), "r"(a1), "r"(a2), "r"(a3), "r"(b0), "r"(b1));
}

__device__ __forceinline__ void ldsm_x4(uint32_t& r0, uint32_t& r1, uint32_t& r2,
                                        uint32_t& r3, uint32_t addr) {
    asm volatile("ldmatrix.sync.aligned.m8n8.x4.shared.b16 {%0,%1,%2,%3}, [%4];"
                 : "=r"(r0), "=r"(r1), "=r"(r2), "=r"(r3) : "r"(addr));
}

__device__ __forceinline__ void fma4(float4& acc, float s, const float4& v) {
    acc.x = fmaf(s, v.x, acc.x);
    acc.y = fmaf(s, v.y, acc.y);
    acc.z = fmaf(s, v.z, acc.z);
    acc.w = fmaf(s, v.w, acc.w);
}

// 8-byte load of 4 fp16 values -> float4
__device__ __forceinline__ float4 ldg_h4(const __half* p) {
    uint2 raw = *(const uint2*)p;
    float2 lo = __half22float2(*reinterpret_cast<__half2*>(&raw.x));
    float2 hi = __half22float2(*reinterpret_cast<__half2*>(&raw.y));
    return make_float4(lo.x, lo.y, hi.x, hi.y);
}

// ---------------- setup kernels ----------------
__global__ void k_zero_deg() {
    int i = blockIdx.x * blockDim.x + threadIdx.x;
    if (i < NN) g_deg[i] = 0;
}

__global__ void k_deg(const int* __restrict__ dst) {
    int e = blockIdx.x * blockDim.x + threadIdx.x;
    if (e < EE) atomicAdd(&g_deg[dst[e]], 1);
}

__global__ void k_dinv() {
    int n = blockIdx.x * blockDim.x + threadIdx.x;
    if (n < NN) {
        int d = g_deg[n];
        g_dinv[n] = (d > 0) ? rsqrtf((float)d) : 0.0f;
    }
}

// ---- 3-phase scan ----
__global__ void k_scan1() {
    __shared__ int red[256];
    int b = blockIdx.x;
    int t = threadIdx.x;
    int base = b * 1024 + t * 4;
    int s = 0;
#pragma unroll
    for (int i = 0; i < 4; i++) {
        int idx = base + i;
        if (idx < NN) s += g_deg[idx];
    }
    red[t] = s;
    __syncthreads();
    for (int off = 128; off > 0; off >>= 1) {
        if (t < off) red[t] += red[t + off];
        __syncthreads();
    }
    if (t == 0) g_bsum[b] = red[0];
}

__global__ void k_scan2() {
    if (threadIdx.x == 0) {
        int acc = 0;
        for (int i = 0; i < SCAN_BLK; i++) {
            g_boff[i] = acc;
            acc += g_bsum[i];
        }
        g_off[NN] = acc;
    }
}

__global__ void k_scan3() {
    __shared__ int pre[256];
    int b = blockIdx.x;
    int t = threadIdx.x;
    int base = b * 1024 + t * 4;
    int d[4];
    int s = 0;
#pragma unroll
    for (int i = 0; i < 4; i++) {
        int idx = base + i;
        d[i] = (idx < NN) ? g_deg[idx] : 0;
        s += d[i];
    }
    pre[t] = s;
    __syncthreads();
    for (int off = 1; off < 256; off <<= 1) {
        int v = (t >= off) ? pre[t - off] : 0;
        __syncthreads();
        pre[t] += v;
        __syncthreads();
    }
    int run = g_boff[b] + pre[t] - s;
#pragma unroll
    for (int i = 0; i < 4; i++) {
        int idx = base + i;
        if (idx < NN) {
            g_off[idx] = run;
            g_fill[idx] = run;
            run += d[i];
        }
    }
}

__global__ void k_fill(const int* __restrict__ src, const int* __restrict__ dst) {
    int e = blockIdx.x * blockDim.x + threadIdx.x;
    if (e < EE) {
        int d = dst[e];
        int s = src[e];
        int pos = atomicAdd(&g_fill[d], 1);
        float w = -g_dinv[s] * g_dinv[d];
        g_srcw[pos] = make_int2(s, __float_as_int(w));
    }
}

__global__ void k_ptr(const int* __restrict__ batch) {
    int n = blockIdx.x * blockDim.x + threadIdx.x;
    if (n >= NN) return;
    int b = batch[n];
    if (n == 0) {
        for (int bb = 0; bb <= b; bb++) g_ptr[bb] = 0;
    } else {
        int pb = batch[n - 1];
        for (int bb = pb + 1; bb <= b; bb++) g_ptr[bb] = n;
    }
    if (n == NN - 1) {
        for (int bb = b + 1; bb <= BB; bb++) g_ptr[bb] = NN;
    }
}

__global__ void k_cnt() {
    int b = threadIdx.x;
    if (b < BB) {
        int c = g_ptr[b + 1] - g_ptr[b];
        g_cnt[b] = (c > 0) ? (float)c : 1.0f;
    }
}

// ---------------- propagation: fp16 gather, fp16 output, NPB nodes per block ----------------
// dst[n, doff+c] = fp16( scale * sum_e w_e * hsrc[src_e, c] + c1*b1[n,c] + c2*b2[n,c] + bias[c] )
template <int NCH, int NPB>
__global__ void __launch_bounds__((NCH / 4) * NPB) k_prop(
    const __half* __restrict__ hsrc, int hstr, int hoff,
    const __half* __restrict__ b1, int b1str, float c1,
    const __half* __restrict__ b2, int b2str, float c2,
    const float* __restrict__ bias, float scale,
    __half* __restrict__ dst, int doff, int dstr) {
    int n = blockIdx.x * NPB + threadIdx.y;
    int c = threadIdx.x * 4;
    int s = g_off[n], e = g_off[n + 1];
    const __half* hb = hsrc + hoff + c;
    float4 a0 = {0, 0, 0, 0}, a1 = a0, a2 = a0, a3 = a0;
    int ed = s;
    for (; ed + 4 <= e; ed += 4) {
        int2 p0 = g_srcw[ed], p1 = g_srcw[ed + 1], p2 = g_srcw[ed + 2], p3 = g_srcw[ed + 3];
        float4 v0 = ldg_h4(hb + (size_t)p0.x * hstr);
        float4 v1 = ldg_h4(hb + (size_t)p1.x * hstr);
        float4 v2 = ldg_h4(hb + (size_t)p2.x * hstr);
        float4 v3 = ldg_h4(hb + (size_t)p3.x * hstr);
        fma4(a0, __int_as_float(p0.y), v0);
        fma4(a1, __int_as_float(p1.y), v1);
        fma4(a2, __int_as_float(p2.y), v2);
        fma4(a3, __int_as_float(p3.y), v3);
    }
    for (; ed < e; ed++) {
        int2 p = g_srcw[ed];
        float4 v = ldg_h4(hb + (size_t)p.x * hstr);
        fma4(a0, __int_as_float(p.y), v);
    }
    float4 r;
    r.x = ((a0.x + a1.x) + (a2.x + a3.x)) * scale;
    r.y = ((a0.y + a1.y) + (a2.y + a3.y)) * scale;
    r.z = ((a0.z + a1.z) + (a2.z + a3.z)) * scale;
    r.w = ((a0.w + a1.w) + (a2.w + a3.w)) * scale;
    if (b1) {
        float4 v = ldg_h4(b1 + (size_t)n * b1str + c);
        r.x += c1 * v.x; r.y += c1 * v.y; r.z += c1 * v.z; r.w += c1 * v.w;
    }
    if (b2) {
        float4 v = ldg_h4(b2 + (size_t)n * b2str + c);
        r.x += c2 * v.x; r.y += c2 * v.y; r.z += c2 * v.z; r.w += c2 * v.w;
    }
    if (bias) {
        r.x += __ldg(bias + c); r.y += __ldg(bias + c + 1);
        r.z += __ldg(bias + c + 2); r.w += __ldg(bias + c + 3);
    }
    __half2* ph = (__half2*)(dst + (size_t)n * dstr + doff + c);
    ph[0] = __floats2half2_rn(r.x, r.y);
    ph[1] = __floats2half2_rn(r.z, r.w);
}

// ---------------- fp16 convert of x ----------------
__global__ void k_convAx(const float* __restrict__ x) {
    int idx = blockIdx.x * blockDim.x + threadIdx.x;
    if (idx >= NN * 128) return;
    int n = idx >> 7;
    int c = idx & 127;
    g_abf[(size_t)n * 384 + c] = __float2half_rn(x[idx]);
}

// ---------------- weight converts ----------------
__global__ void k_convW(const float* __restrict__ W, int cin, int cout) {
    int K3 = 3 * cin;
    int idx = blockIdx.x * blockDim.x + threadIdx.x;
    if (idx >= cout * K3) return;
    int n = idx / K3;
    int R = idx - n * K3;
    g_wbf[(size_t)n * K3 + R] = __float2half_rn(W[(size_t)R * cout + n]);
}

__global__ void k_convWB(const float* __restrict__ W, int cin, int cout) {
    int idx = blockIdx.x * blockDim.x + threadIdx.x;
    if (idx >= 3 * cout * cin) return;
    int n = idx / cin;
    int k = idx - n * cin;
    int j = n / cout;
    int nc = n - j * cout;
    g_wbf[(size_t)n * cin + k] = __float2half_rn(W[((size_t)j * cin + k) * cout + nc]);
}

// ---------------- tensor-core GEMM via mma.sync + ldmatrix (fp16 in, fp16 out) ----------------
#define BM 128
#define BN 128
#define BK 32
#define ASTR 40

__global__ void __launch_bounds__(256)
k_gemm_mma(const float* __restrict__ bias, __half* __restrict__ Ch, int K, int Ncols) {
    __shared__ __align__(16) __half As[2][BM * ASTR];
    __shared__ __align__(16) __half Bs[2][BN * ASTR];
    int tid = threadIdx.x;
    int lane = tid & 31;
    int wid = tid >> 5;
    int wm = wid >> 2;
    int wn = wid & 3;
    int m0 = blockIdx.x * BM;
    int n0 = blockIdx.y * BN;
    int nch = K / BK;

    float c[4][4][4] = {};

    int lrow = tid >> 2;
    int lcol = (tid & 3) * 8;
    uint32_t sa = smem_u32(As);
    uint32_t sb = smem_u32(Bs);
    uint32_t dstA = sa + (uint32_t)(lrow * ASTR + lcol) * 2;
    uint32_t dstB = sb + (uint32_t)(lrow * ASTR + lcol) * 2;
    const uint32_t bufsz = (uint32_t)BM * ASTR * 2;

    int qr = lane >> 2;
    int qc = (lane & 3) * 2;

    uint32_t a_off = (uint32_t)((wm * 64 + (lane & 15)) * ASTR + (lane >> 4) * 8) * 2;
    int bg_ = lane >> 3;
    uint32_t b_off = (uint32_t)((wn * 32 + (bg_ >> 1) * 8 + (lane & 7)) * ASTR
                                + (bg_ & 1) * 8) * 2;

    {
        const __half* ag = g_abf + (size_t)(m0 + lrow) * K + lcol;
        const __half* bg = g_wbf + (size_t)(n0 + lrow) * K + lcol;
        cp_async16(dstA, ag);
        cp_async16(dstA + 64u * ASTR * 2, ag + (size_t)64 * K);
        cp_async16(dstB, bg);
        cp_async16(dstB + 64u * ASTR * 2, bg + (size_t)64 * K);
        CP_COMMIT();
    }

    for (int ch = 0; ch < nch; ch++) {
        int buf = ch & 1;
        if (ch + 1 < nch) {
            int kg = (ch + 1) * BK;
            const __half* ag = g_abf + (size_t)(m0 + lrow) * K + kg + lcol;
            const __half* bg = g_wbf + (size_t)(n0 + lrow) * K + kg + lcol;
            uint32_t da = dstA + (buf ^ 1) * bufsz;
            uint32_t db = dstB + (buf ^ 1) * bufsz;
            cp_async16(da, ag);
            cp_async16(da + 64u * ASTR * 2, ag + (size_t)64 * K);
            cp_async16(db, bg);
            cp_async16(db + 64u * ASTR * 2, bg + (size_t)64 * K);
            CP_COMMIT();
            CP_WAIT(1);
        } else {
            CP_WAIT(0);
        }
        __syncthreads();

        uint32_t abase = sa + buf * bufsz + a_off;
        uint32_t bbase = sb + buf * bufsz + b_off;
#pragma unroll
        for (int ks = 0; ks < 2; ks++) {
            uint32_t kso = (uint32_t)(ks * 16) * 2;
            uint32_t a[4][4];
#pragma unroll
            for (int mi = 0; mi < 4; mi++)
                ldsm_x4(a[mi][0], a[mi][1], a[mi][2], a[mi][3],
                        abase + kso + (uint32_t)(mi * 16 * ASTR) * 2);
            uint32_t b[4][2];
#pragma unroll
            for (int nj = 0; nj < 2; nj++)
                ldsm_x4(b[nj * 2][0], b[nj * 2][1], b[nj * 2 + 1][0], b[nj * 2 + 1][1],
                        bbase + kso + (uint32_t)(nj * 16 * ASTR) * 2);
#pragma unroll
            for (int mi = 0; mi < 4; mi++)
#pragma unroll
                for (int ni = 0; ni < 4; ni++)
                    mma_f16(c[mi][ni], a[mi][0], a[mi][1], a[mi][2], a[mi][3],
                            b[ni][0], b[ni][1]);
        }
        __syncthreads();
    }

    float bv0[4], bv1[4];
#pragma unroll
    for (int ni = 0; ni < 4; ni++) {
        int col = n0 + wn * 32 + ni * 8 + qc;
        bv0[ni] = bias ? bias[col] : 0.0f;
        bv1[ni] = bias ? bias[col + 1] : 0.0f;
    }
#pragma unroll
    for (int mi = 0; mi < 4; mi++) {
        int r = m0 + wm * 64 + mi * 16 + qr;
#pragma unroll
        for (int ni = 0; ni < 4; ni++) {
            int col = n0 + wn * 32 + ni * 8 + qc;
            if (r < NN)
                *(__half2*)&Ch[(size_t)r * Ncols + col] =
                    __floats2half2_rn(c[mi][ni][0] + bv0[ni], c[mi][ni][1] + bv1[ni]);
            if (r + 8 < NN)
                *(__half2*)&Ch[(size_t)(r + 8) * Ncols + col] =
                    __floats2half2_rn(c[mi][ni][2] + bv0[ni], c[mi][ni][3] + bv1[ni]);
        }
    }
}

// ---------------- GraphNorm: chip-wide 4-phase (fp16 in/out) ----------------
__global__ void k_gnzero(int cout) {
    int idx = blockIdx.x * blockDim.x + threadIdx.x;
    if (idx < BB * cout) {
        g_s1[idx] = 0.f;
        g_s2[idx] = 0.f;
    }
}

__global__ void k_gnstat(const __half* __restrict__ X, int cout) {
    int bg = blockIdx.x;
    int ci = threadIdx.x;
    int c = blockIdx.y * 128 + ci;
    int s = g_ptr[bg], e = g_ptr[bg + 1];
    int len = e - s;
    int chunk = (len + GN_CHK - 1) / GN_CHK;
    int ns = s + blockIdx.z * chunk;
    int ne = min(ns + chunk, e);
    float s1 = 0.f, s2 = 0.f;
    for (int n = ns; n < ne; n++) {
        float v = __half2float(X[(size_t)n * cout + c]);
        s1 += v;
        s2 = fmaf(v, v, s2);
    }
    if (ns < ne) {
        atomicAdd(&g_s1[bg * cout + c], s1);
        atomicAdd(&g_s2[bg * cout + c], s2);
    }
}

__global__ void k_gnfin(const float* __restrict__ w, const float* __restrict__ ms,
                        int cout) {
    int idx = blockIdx.x * blockDim.x + threadIdx.x;
    if (idx >= BB * cout) return;
    int bg = idx / cout;
    int c = idx - bg * cout;
    float invc = 1.0f / g_cnt[bg];
    float mean = g_s1[idx] * invc;
    float m = ms[c] * mean;
    float var = fmaxf(g_s2[idx] * invc - 2.0f * m * mean + m * m, 0.0f);
    g_s1[idx] = m;
    g_s2[idx] = w[c] * rsqrtf(var + GN_EPS);
}

// elementwise normalize + leaky relu: fp16 in, fp16 out; 8 halves/thread
__global__ void k_gnnorm(const __half* __restrict__ X, const float* __restrict__ b,
                         const int* __restrict__ batch, int cout, int lc,
                         __half* __restrict__ dst, int dstr) {
    int idx = blockIdx.x * blockDim.x + threadIdx.x;
    int base = idx * 8;
    if (base >= NN * cout) return;
    int n = base >> lc;
    int c = base & (cout - 1);
    int bg = batch[n];
    const float* s1 = g_s1 + bg * cout + c;
    const float* s2 = g_s2 + bg * cout + c;
    uint4 raw = *(const uint4*)(X + base);
    __half2* hp = (__half2*)&raw;
    __half2 ov[4];
#pragma unroll
    for (int i = 0; i < 4; i++) {
        float2 v = __half22float2(hp[i]);
        float t0 = s2[2 * i] * (v.x - s1[2 * i]) + __ldg(b + c + 2 * i);
        float t1 = s2[2 * i + 1] * (v.y - s1[2 * i + 1]) + __ldg(b + c + 2 * i + 1);
        t0 = (t0 >= 0.f) ? t0 : 0.2f * t0;
        t1 = (t1 >= 0.f) ? t1 : 0.2f * t1;
        ov[i] = __floats2half2_rn(t0, t1);
    }
    *(uint4*)(dst + (size_t)n * dstr + c) = *(uint4*)ov;
}

// ---------------- residual + mean pool (h fp16, x fp32) ----------------
__global__ void k_pool(const __half* __restrict__ h, const float* __restrict__ x) {
    int bg = blockIdx.x;
    int c = threadIdx.x;  // 128
    int s = g_ptr[bg];
    int e = g_ptr[bg + 1];
    float sa = 0.f, sb = 0.f, sc = 0.f, sd = 0.f;
    int n = s;
    for (; n + 4 <= e; n += 4) {
        sa += __half2float(h[(size_t)n * 128 + c]) + x[(size_t)n * 128 + c];
        sb += __half2float(h[(size_t)(n + 1) * 128 + c]) + x[(size_t)(n + 1) * 128 + c];
        sc += __half2float(h[(size_t)(n + 2) * 128 + c]) + x[(size_t)(n + 2) * 128 + c];
        sd += __half2float(h[(size_t)(n + 3) * 128 + c]) + x[(size_t)(n + 3) * 128 + c];
    }
    for (; n < e; n++) sa += __half2float(h[(size_t)n * 128 + c]) + x[(size_t)n * 128 + c];
    g_pool[bg * 128 + c] = ((sa + sb) + (sc + sd)) / g_cnt[bg];
}

// ---------------- MLP head ----------------
__global__ void k_head(const float* __restrict__ W1, const float* __restrict__ b1,
                       const float* __restrict__ W2, const float* __restrict__ b2,
                       float* __restrict__ out) {
    int bg = blockIdx.x;
    __shared__ float hid[64];
    int j = threadIdx.x;  // 64
    float s = b1[j];
    for (int i = 0; i < 128; i++) s += g_pool[bg * 128 + i] * W1[i * 64 + j];
    hid[j] = tanhf(s);
    __syncthreads();
    if (j < 10) {
        float o = b2[j];
        for (int i = 0; i < 64; i++) o += hid[i] * W2[i * 10 + j];
        out[bg * 10 + j] = o;
    }
}

// ---------------- host orchestration ----------------
static void prop_launch(int nch, const __half* hsrc, int hstr, int hoff,
                        const __half* b1, int b1str, float c1,
                        const __half* b2, int b2str, float c2,
                        const float* bias, float scale,
                        __half* dst, int doff, int dstr) {
    if (nch == 128) {
        k_prop<128, 4><<<NN / 4, dim3(32, 4)>>>(hsrc, hstr, hoff, b1, b1str, c1,
                                                b2, b2str, c2, bias, scale,
                                                dst, doff, dstr);
    } else {
        k_prop<256, 2><<<NN / 2, dim3(64, 2)>>>(hsrc, hstr, hoff, b1, b1str, c1,
                                                b2, b2str, c2, bias, scale,
                                                dst, doff, dstr);
    }
}

static void gn_launch(const __half* X, const float* w, const float* b, const float* ms,
                      const int* batch, int cout, int lc, __half* dst, int dstr) {
    k_gnzero<<<cdiv(BB * cout, 256), 256>>>(cout);
    dim3 gs(BB, cout / 128, GN_CHK);
    k_gnstat<<<gs, 128>>>(X, cout);
    k_gnfin<<<cdiv(BB * cout, 256), 256>>>(w, ms, cout);
    k_gnnorm<<<cdiv(NN * cout / 8, 256), 256>>>(X, b, batch, cout, lc, dst, dstr);
}

extern "C" void kernel_launch(void* const* d_in, const int* in_sizes, int n_in,
                              void* d_out, int out_size) {
    const float* x = (const float*)d_in[0];
    const int* ei = (const int*)d_in[1];
    const int* src = ei;
    const int* dst = ei + EE;
    const int* batch = (const int*)d_in[2];

    __half *abf, *hbf, *cbf, *ubf;
    cudaGetSymbolAddress((void**)&abf, g_abf);
    cudaGetSymbolAddress((void**)&hbf, g_hbf);
    cudaGetSymbolAddress((void**)&cbf, g_cbf);
    cudaGetSymbolAddress((void**)&ubf, g_ubf);

    // ---- setup: degrees, CSR, graph segments ----
    k_zero_deg<<<cdiv(NN, 256), 256>>>();
    k_deg<<<cdiv(EE, 256), 256>>>(dst);
    k_dinv<<<cdiv(NN, 256), 256>>>();
    k_scan1<<<SCAN_BLK, 256>>>();
    k_scan2<<<1, 32>>>();
    k_scan3<<<SCAN_BLK, 256>>>();
    k_fill<<<cdiv(EE, 256), 256>>>(src, dst);
    k_ptr<<<cdiv(NN, 256), 256>>>(batch);
    k_cnt<<<1, 64>>>();

    // ================= Layer 1 (mode A, 128 -> 256, K = 384) =================
    {
        const int cin = 128, cout = 256, K = 3 * cin;
        k_convAx<<<cdiv(NN * 128, 256), 256>>>(x);
        // t1 = prop(x)
        prop_launch(cin, abf, K, 0, nullptr, 0, 0.f, nullptr, 0, 0.f, nullptr, 1.0f,
                    abf, cin, K);
        // t2 = 2*prop(t1) - x
        prop_launch(cin, abf, K, cin, abf, K, -1.0f, nullptr, 0, 0.f, nullptr, 2.0f,
                    abf, 2 * cin, K);
        k_convW<<<cdiv(cout * K, 256), 256>>>((const float*)d_in[3], cin, cout);
        dim3 gg(MPAD / 128, cout / 128);
        k_gemm_mma<<<gg, 256>>>((const float*)d_in[4], hbf, K, cout);
        // GN: hbf -> abf (layer-2 A, stride 768, h at offset 0)
        gn_launch(hbf, (const float*)d_in[5], (const float*)d_in[6],
                  (const float*)d_in[7], batch, cout, 8, abf, 3 * 256);
    }

    // ================= Layer 2 (mode A, 256 -> 512, K = 768) =================
    {
        const int cin = 256, cout = 512, K = 3 * cin;
        prop_launch(cin, abf, K, 0, nullptr, 0, 0.f, nullptr, 0, 0.f, nullptr, 1.0f,
                    abf, cin, K);
        prop_launch(cin, abf, K, cin, abf, K, -1.0f, nullptr, 0, 0.f, nullptr, 2.0f,
                    abf, 2 * cin, K);
        k_convW<<<cdiv(cout * K, 256), 256>>>((const float*)d_in[8], cin, cout);
        dim3 gg(MPAD / 128, cout / 128);
        k_gemm_mma<<<gg, 256>>>((const float*)d_in[9], hbf, K, cout);
        // GN: hbf -> abf (layer-3 A, stride 512)
        gn_launch(hbf, (const float*)d_in[10], (const float*)d_in[11],
                  (const float*)d_in[12], batch, cout, 9, abf, 512);
    }

    // ================= Layer 3 (mode B, 512 -> 256, K = 512) =================
    {
        const int cin = 512, cout = 256;
        k_convWB<<<cdiv(3 * cout * cin, 256), 256>>>((const float*)d_in[13], cin, cout);
        dim3 gg(MPAD / 128, (3 * cout) / 128);
        k_gemm_mma<<<gg, 256>>>(nullptr, cbf, cin, 3 * cout);  // cbf = [P0|P1|P2]
        // u = P1 + 2*prop(P2)
        prop_launch(cout, cbf, 3 * cout, 2 * cout, cbf + cout, 3 * cout, 1.0f,
                    nullptr, 0, 0.f, nullptr, 2.0f, ubf, 0, cout);
        // h = prop(u) + P0 - P2 + bias -> hbf
        prop_launch(cout, ubf, cout, 0, cbf, 3 * cout, 1.0f, cbf + 2 * cout, 3 * cout, -1.0f,
                    (const float*)d_in[14], 1.0f, hbf, 0, cout);
        // GN: hbf -> abf (layer-4 A, stride 256)
        gn_launch(hbf, (const float*)d_in[15], (const float*)d_in[16],
                  (const float*)d_in[17], batch, cout, 8, abf, 256);
    }

    // ================= Layer 4 (mode B, 256 -> 128, K = 256) =================
    {
        const int cin = 256, cout = 128;
        k_convWB<<<cdiv(3 * cout * cin, 256), 256>>>((const float*)d_in[18], cin, cout);
        dim3 gg(MPAD / 128, (3 * cout) / 128);
        k_gemm_mma<<<gg, 256>>>(nullptr, cbf, cin, 3 * cout);
        prop_launch(cout, cbf, 3 * cout, 2 * cout, cbf + cout, 3 * cout, 1.0f,
                    nullptr, 0, 0.f, nullptr, 2.0f, ubf, 0, cout);
        prop_launch(cout, ubf, cout, 0, cbf, 3 * cout, 1.0f, cbf + 2 * cout, 3 * cout, -1.0f,
                    (const float*)d_in[19], 1.0f, hbf, 0, cout);
        // GN in-place: hbf -> hbf (stride 128)
        gn_launch(hbf, (const float*)d_in[20], (const float*)d_in[21],
                  (const float*)d_in[22], batch, cout, 7, hbf, 128);
    }

    // ---- residual + pool + head ----
    k_pool<<<BB, 128>>>(hbf, x);
    k_head<<<BB, 64>>>((const float*)d_in[23], (const float*)d_in[24],
                       (const float*)d_in[25], (const float*)d_in[26],
                       (float*)d_out);
}

// round 14
// speedup vs baseline: 1.0857x; 1.0857x over previous
#include <cuda_runtime.h>
#include <cuda_fp16.h>
#include <math.h>
#include <cstdint>

#define NN 50000
#define EE 800000
#define BB 50
#define GN_EPS 1e-5f
#define MPAD 50048   // 391 * 128
#define SCAN_BLK 49  // ceil(NN / 1024)
#define GN_CHK 8

// ---------------- scratch (static device memory; no allocations) ----------------
__device__ float g_f0[(size_t)NN * 512];
__device__ float g_f1[(size_t)NN * 512];
__device__ __half g_abf[(size_t)MPAD * 1536];   // fp16 A; pad rows read-only garbage (discarded)
__device__ __half g_wbf[(size_t)512 * 2304];    // fp16 W (n-major)
__device__ __half g_cbf[(size_t)NN * 768];      // fp16 [P0|P1|P2] (mode B)
__device__ __half g_ubf[(size_t)NN * 256];      // fp16 u (mode B)
__device__ float g_s1[BB * 512];
__device__ float g_s2[BB * 512];
__device__ int   g_deg[NN];
__device__ float g_dinv[NN];
__device__ int   g_off[NN + 1];
__device__ int   g_fill[NN];
__device__ int   g_bsum[SCAN_BLK];
__device__ int   g_boff[SCAN_BLK];
__device__ int2  g_srcw[EE];   // {src, float_bits(w)}
__device__ int   g_ptr[BB + 1];
__device__ float g_cnt[BB];
__device__ float g_pool[BB * 128];

static inline int cdiv(int a, int b) { return (a + b - 1) / b; }

// ---------------- PTX helpers ----------------
__device__ __forceinline__ uint32_t smem_u32(const void* p) {
    uint32_t a;
    asm("{ .reg .u64 t; cvta.to.shared.u64 t, %1; cvt.u32.u64 %0, t; }" : "=r"(a) : "l"(p));
    return a;
}

__device__ __forceinline__ void cp_async16(uint32_t dst, const void* src) {
    asm volatile("cp.async.cg.shared.global [%0], [%1], 16;\n" :: "r"(dst), "l"(src));
}
#define CP_COMMIT() asm volatile("cp.async.commit_group;\n" ::: "memory")
#define CP_WAIT(n)  asm volatile("cp.async.wait_group %0;\n" :: "n"(n) : "memory")

__device__ __forceinline__ void mma_f16(float* c, uint32_t a0, uint32_t a1, uint32_t a2,
                                        uint32_t a3, uint32_t b0, uint32_t b1) {
    asm volatile(
        "mma.sync.aligned.m16n8k16.row.col.f32.f16.f16.f32 "
        "{%0,%1,%2,%3}, {%4,%5,%6,%7}, {%8,%9}, {%0,%1,%2,%3};"
        : "+f"(c[0]), "+f"(c[1]), "+f"(c[2]), "+f"(c[3])
        : "r"(a0), "r"(a1), "r"(a2), "r"(a3), "r"(b0), "r"(b1));
}

__device__ __forceinline__ void ldsm_x4(uint32_t& r0, uint32_t& r1, uint32_t& r2,
                                        uint32_t& r3, uint32_t addr) {
    asm volatile("ldmatrix.sync.aligned.m8n8.x4.shared.b16 {%0,%1,%2,%3}, [%4];"
                 : "=r"(r0), "=r"(r1), "=r"(r2), "=r"(r3) : "r"(addr));
}

// fma of 8 fp16 channels (raw uint4) into 8 fp32 accumulators
__device__ __forceinline__ void fma8(float* acc, float w, const uint4& raw) {
    const __half2* hp = (const __half2*)&raw;
#pragma unroll
    for (int i = 0; i < 4; i++) {
        float2 v = __half22float2(hp[i]);
        acc[2 * i] = fmaf(w, v.x, acc[2 * i]);
        acc[2 * i + 1] = fmaf(w, v.y, acc[2 * i + 1]);
    }
}

// ---------------- setup kernels ----------------
__global__ void k_zero_deg() {
    int i = blockIdx.x * blockDim.x + threadIdx.x;
    if (i < NN) g_deg[i] = 0;
}

__global__ void k_deg(const int* __restrict__ dst) {
    int e = blockIdx.x * blockDim.x + threadIdx.x;
    if (e < EE) atomicAdd(&g_deg[dst[e]], 1);
}

__global__ void k_dinv() {
    int n = blockIdx.x * blockDim.x + threadIdx.x;
    if (n < NN) {
        int d = g_deg[n];
        g_dinv[n] = (d > 0) ? rsqrtf((float)d) : 0.0f;
    }
}

// ---- 3-phase scan ----
__global__ void k_scan1() {
    __shared__ int red[256];
    int b = blockIdx.x;
    int t = threadIdx.x;
    int base = b * 1024 + t * 4;
    int s = 0;
#pragma unroll
    for (int i = 0; i < 4; i++) {
        int idx = base + i;
        if (idx < NN) s += g_deg[idx];
    }
    red[t] = s;
    __syncthreads();
    for (int off = 128; off > 0; off >>= 1) {
        if (t < off) red[t] += red[t + off];
        __syncthreads();
    }
    if (t == 0) g_bsum[b] = red[0];
}

__global__ void k_scan2() {
    if (threadIdx.x == 0) {
        int acc = 0;
        for (int i = 0; i < SCAN_BLK; i++) {
            g_boff[i] = acc;
            acc += g_bsum[i];
        }
        g_off[NN] = acc;
    }
}

__global__ void k_scan3() {
    __shared__ int pre[256];
    int b = blockIdx.x;
    int t = threadIdx.x;
    int base = b * 1024 + t * 4;
    int d[4];
    int s = 0;
#pragma unroll
    for (int i = 0; i < 4; i++) {
        int idx = base + i;
        d[i] = (idx < NN) ? g_deg[idx] : 0;
        s += d[i];
    }
    pre[t] = s;
    __syncthreads();
    for (int off = 1; off < 256; off <<= 1) {
        int v = (t >= off) ? pre[t - off] : 0;
        __syncthreads();
        pre[t] += v;
        __syncthreads();
    }
    int run = g_boff[b] + pre[t] - s;
#pragma unroll
    for (int i = 0; i < 4; i++) {
        int idx = base + i;
        if (idx < NN) {
            g_off[idx] = run;
            g_fill[idx] = run;
            run += d[i];
        }
    }
}

__global__ void k_fill(const int* __restrict__ src, const int* __restrict__ dst) {
    int e = blockIdx.x * blockDim.x + threadIdx.x;
    if (e < EE) {
        int d = dst[e];
        int s = src[e];
        int pos = atomicAdd(&g_fill[d], 1);
        float w = -g_dinv[s] * g_dinv[d];
        g_srcw[pos] = make_int2(s, __float_as_int(w));
    }
}

__global__ void k_ptr(const int* __restrict__ batch) {
    int n = blockIdx.x * blockDim.x + threadIdx.x;
    if (n >= NN) return;
    int b = batch[n];
    if (n == 0) {
        for (int bb = 0; bb <= b; bb++) g_ptr[bb] = 0;
    } else {
        int pb = batch[n - 1];
        for (int bb = pb + 1; bb <= b; bb++) g_ptr[bb] = n;
    }
    if (n == NN - 1) {
        for (int bb = b + 1; bb <= BB; bb++) g_ptr[bb] = NN;
    }
}

__global__ void k_cnt() {
    int b = threadIdx.x;
    if (b < BB) {
        int c = g_ptr[b + 1] - g_ptr[b];
        g_cnt[b] = (c > 0) ? (float)c : 1.0f;
    }
}

// ---------------- propagation: 16B fp16 gathers, 8 channels/thread ----------------
// out[n,c] = scale * sum_e w_e * hsrc[src_e, c] + c1*b1[n,c] + c2*b2[n,c] + bias[c]
template <int NCH, int NPB>
__global__ void __launch_bounds__((NCH / 8) * NPB) k_prop(
    const __half* __restrict__ hsrc, int hstr, int hoff,
    const __half* __restrict__ b1, int b1str, float c1,
    const __half* __restrict__ b2, int b2str, float c2,
    const float* __restrict__ bias, float scale,
    float* __restrict__ out, int ostr,
    __half* abf, int aoff, int astr) {
    int n = blockIdx.x * NPB + threadIdx.y;
    int c = threadIdx.x * 8;
    int s = g_off[n], e = g_off[n + 1];
    const __half* hb = hsrc + hoff + c;
    float a0[8] = {}, a1[8] = {};
    int ed = s;
    for (; ed + 4 <= e; ed += 4) {
        int2 p0 = g_srcw[ed], p1 = g_srcw[ed + 1], p2 = g_srcw[ed + 2], p3 = g_srcw[ed + 3];
        uint4 r0 = *(const uint4*)(hb + (size_t)p0.x * hstr);
        uint4 r1 = *(const uint4*)(hb + (size_t)p1.x * hstr);
        uint4 r2 = *(const uint4*)(hb + (size_t)p2.x * hstr);
        uint4 r3 = *(const uint4*)(hb + (size_t)p3.x * hstr);
        fma8(a0, __int_as_float(p0.y), r0);
        fma8(a1, __int_as_float(p1.y), r1);
        fma8(a0, __int_as_float(p2.y), r2);
        fma8(a1, __int_as_float(p3.y), r3);
    }
    for (; ed < e; ed++) {
        int2 p = g_srcw[ed];
        uint4 r = *(const uint4*)(hb + (size_t)p.x * hstr);
        fma8(a0, __int_as_float(p.y), r);
    }
    float r[8];
#pragma unroll
    for (int i = 0; i < 8; i++) r[i] = (a0[i] + a1[i]) * scale;
    if (b1) {
        uint4 raw = *(const uint4*)(b1 + (size_t)n * b1str + c);
        const __half2* hp = (const __half2*)&raw;
#pragma unroll
        for (int i = 0; i < 4; i++) {
            float2 v = __half22float2(hp[i]);
            r[2 * i] += c1 * v.x;
            r[2 * i + 1] += c1 * v.y;
        }
    }
    if (b2) {
        uint4 raw = *(const uint4*)(b2 + (size_t)n * b2str + c);
        const __half2* hp = (const __half2*)&raw;
#pragma unroll
        for (int i = 0; i < 4; i++) {
            float2 v = __half22float2(hp[i]);
            r[2 * i] += c2 * v.x;
            r[2 * i + 1] += c2 * v.y;
        }
    }
    if (bias) {
#pragma unroll
        for (int i = 0; i < 8; i++) r[i] += __ldg(bias + c + i);
    }
    if (out) {
        *(float4*)(out + (size_t)n * ostr + c) = make_float4(r[0], r[1], r[2], r[3]);
        *(float4*)(out + (size_t)n * ostr + c + 4) = make_float4(r[4], r[5], r[6], r[7]);
    }
    if (abf) {
        __half2 ov[4];
#pragma unroll
        for (int i = 0; i < 4; i++) ov[i] = __floats2half2_rn(r[2 * i], r[2 * i + 1]);
        *(uint4*)(abf + (size_t)n * astr + aoff + c) = *(uint4*)ov;
    }
}

// ---------------- fp16 convert of x ----------------
__global__ void k_convAx(const float* __restrict__ x) {
    int idx = blockIdx.x * blockDim.x + threadIdx.x;
    if (idx >= NN * 128) return;
    int n = idx >> 7;
    int c = idx & 127;
    g_abf[(size_t)n * 384 + c] = __float2half_rn(x[idx]);
}

// ---------------- weight converts ----------------
__global__ void k_convW(const float* __restrict__ W, int cin, int cout) {
    int K3 = 3 * cin;
    int idx = blockIdx.x * blockDim.x + threadIdx.x;
    if (idx >= cout * K3) return;
    int n = idx / K3;
    int R = idx - n * K3;
    g_wbf[(size_t)n * K3 + R] = __float2half_rn(W[(size_t)R * cout + n]);
}

__global__ void k_convWB(const float* __restrict__ W, int cin, int cout) {
    int idx = blockIdx.x * blockDim.x + threadIdx.x;
    if (idx >= 3 * cout * cin) return;
    int n = idx / cin;
    int k = idx - n * cin;
    int j = n / cout;
    int nc = n - j * cout;
    g_wbf[(size_t)n * cin + k] = __float2half_rn(W[((size_t)j * cin + k) * cout + nc]);
}

// ---------------- tensor-core GEMM via mma.sync + ldmatrix (fp16) ----------------
#define BM 128
#define BN 128
#define BK 32
#define ASTR 40

__global__ void __launch_bounds__(256)
k_gemm_mma(const float* __restrict__ bias, float* __restrict__ C,
           __half* __restrict__ Ch, int K, int Ncols) {
    __shared__ __align__(16) __half As[2][BM * ASTR];
    __shared__ __align__(16) __half Bs[2][BN * ASTR];
    int tid = threadIdx.x;
    int lane = tid & 31;
    int wid = tid >> 5;
    int wm = wid >> 2;
    int wn = wid & 3;
    int m0 = blockIdx.x * BM;
    int n0 = blockIdx.y * BN;
    int nch = K / BK;

    float c[4][4][4] = {};

    int lrow = tid >> 2;
    int lcol = (tid & 3) * 8;
    uint32_t sa = smem_u32(As);
    uint32_t sb = smem_u32(Bs);
    uint32_t dstA = sa + (uint32_t)(lrow * ASTR + lcol) * 2;
    uint32_t dstB = sb + (uint32_t)(lrow * ASTR + lcol) * 2;
    const uint32_t bufsz = (uint32_t)BM * ASTR * 2;

    int qr = lane >> 2;
    int qc = (lane & 3) * 2;

    uint32_t a_off = (uint32_t)((wm * 64 + (lane & 15)) * ASTR + (lane >> 4) * 8) * 2;
    int bg_ = lane >> 3;
    uint32_t b_off = (uint32_t)((wn * 32 + (bg_ >> 1) * 8 + (lane & 7)) * ASTR
                                + (bg_ & 1) * 8) * 2;

    {
        const __half* ag = g_abf + (size_t)(m0 + lrow) * K + lcol;
        const __half* bg = g_wbf + (size_t)(n0 + lrow) * K + lcol;
        cp_async16(dstA, ag);
        cp_async16(dstA + 64u * ASTR * 2, ag + (size_t)64 * K);
        cp_async16(dstB, bg);
        cp_async16(dstB + 64u * ASTR * 2, bg + (size_t)64 * K);
        CP_COMMIT();
    }

    for (int ch = 0; ch < nch; ch++) {
        int buf = ch & 1;
        if (ch + 1 < nch) {
            int kg = (ch + 1) * BK;
            const __half* ag = g_abf + (size_t)(m0 + lrow) * K + kg + lcol;
            const __half* bg = g_wbf + (size_t)(n0 + lrow) * K + kg + lcol;
            uint32_t da = dstA + (buf ^ 1) * bufsz;
            uint32_t db = dstB + (buf ^ 1) * bufsz;
            cp_async16(da, ag);
            cp_async16(da + 64u * ASTR * 2, ag + (size_t)64 * K);
            cp_async16(db, bg);
            cp_async16(db + 64u * ASTR * 2, bg + (size_t)64 * K);
            CP_COMMIT();
            CP_WAIT(1);
        } else {
            CP_WAIT(0);
        }
        __syncthreads();

        uint32_t abase = sa + buf * bufsz + a_off;
        uint32_t bbase = sb + buf * bufsz + b_off;
#pragma unroll
        for (int ks = 0; ks < 2; ks++) {
            uint32_t kso = (uint32_t)(ks * 16) * 2;
            uint32_t a[4][4];
#pragma unroll
            for (int mi = 0; mi < 4; mi++)
                ldsm_x4(a[mi][0], a[mi][1], a[mi][2], a[mi][3],
                        abase + kso + (uint32_t)(mi * 16 * ASTR) * 2);
            uint32_t b[4][2];
#pragma unroll
            for (int nj = 0; nj < 2; nj++)
                ldsm_x4(b[nj * 2][0], b[nj * 2][1], b[nj * 2 + 1][0], b[nj * 2 + 1][1],
                        bbase + kso + (uint32_t)(nj * 16 * ASTR) * 2);
#pragma unroll
            for (int mi = 0; mi < 4; mi++)
#pragma unroll
                for (int ni = 0; ni < 4; ni++)
                    mma_f16(c[mi][ni], a[mi][0], a[mi][1], a[mi][2], a[mi][3],
                            b[ni][0], b[ni][1]);
        }
        __syncthreads();
    }

    float bv0[4], bv1[4];
#pragma unroll
    for (int ni = 0; ni < 4; ni++) {
        int col = n0 + wn * 32 + ni * 8 + qc;
        bv0[ni] = bias ? bias[col] : 0.0f;
        bv1[ni] = bias ? bias[col + 1] : 0.0f;
    }
#pragma unroll
    for (int mi = 0; mi < 4; mi++) {
        int r = m0 + wm * 64 + mi * 16 + qr;
#pragma unroll
        for (int ni = 0; ni < 4; ni++) {
            int col = n0 + wn * 32 + ni * 8 + qc;
            if (r < NN) {
                float va = c[mi][ni][0] + bv0[ni];
                float vb = c[mi][ni][1] + bv1[ni];
                if (C) *(float2*)&C[(size_t)r * Ncols + col] = make_float2(va, vb);
                if (Ch) *(__half2*)&Ch[(size_t)r * Ncols + col] = __floats2half2_rn(va, vb);
            }
            if (r + 8 < NN) {
                float va = c[mi][ni][2] + bv0[ni];
                float vb = c[mi][ni][3] + bv1[ni];
                if (C) *(float2*)&C[(size_t)(r + 8) * Ncols + col] = make_float2(va, vb);
                if (Ch) *(__half2*)&Ch[(size_t)(r + 8) * Ncols + col] = __floats2half2_rn(va, vb);
            }
        }
    }
}

// ---------------- GraphNorm: chip-wide 4-phase ----------------
__global__ void k_gnzero(int cout) {
    int idx = blockIdx.x * blockDim.x + threadIdx.x;
    if (idx < BB * cout) {
        g_s1[idx] = 0.f;
        g_s2[idx] = 0.f;
    }
}

__global__ void k_gnstat(const float* __restrict__ X, int cout) {
    int bg = blockIdx.x;
    int ci = threadIdx.x;
    int c = blockIdx.y * 128 + ci;
    int s = g_ptr[bg], e = g_ptr[bg + 1];
    int len = e - s;
    int chunk = (len + GN_CHK - 1) / GN_CHK;
    int ns = s + blockIdx.z * chunk;
    int ne = min(ns + chunk, e);
    float s1 = 0.f, s2 = 0.f;
    for (int n = ns; n < ne; n++) {
        float v = X[(size_t)n * cout + c];
        s1 += v;
        s2 = fmaf(v, v, s2);
    }
    if (ns < ne) {
        atomicAdd(&g_s1[bg * cout + c], s1);
        atomicAdd(&g_s2[bg * cout + c], s2);
    }
}

__global__ void k_gnfin(const float* __restrict__ w, const float* __restrict__ ms,
                        int cout) {
    int idx = blockIdx.x * blockDim.x + threadIdx.x;
    if (idx >= BB * cout) return;
    int bg = idx / cout;
    int c = idx - bg * cout;
    float invc = 1.0f / g_cnt[bg];
    float mean = g_s1[idx] * invc;
    float m = ms[c] * mean;
    float var = fmaxf(g_s2[idx] * invc - 2.0f * m * mean + m * m, 0.0f);
    g_s1[idx] = m;
    g_s2[idx] = w[c] * rsqrtf(var + GN_EPS);
}

// elementwise normalize + leaky relu; float4; optional fp16 write
__global__ void k_gnnorm(float* __restrict__ X, const float* __restrict__ b,
                         const int* __restrict__ batch, int cout, int lc,
                         __half* abf, int astr) {
    int idx = blockIdx.x * blockDim.x + threadIdx.x;
    int base = idx * 4;
    if (base >= NN * cout) return;
    int n = base >> lc;
    int c = base & (cout - 1);
    int bg = batch[n];
    float4 v = *(float4*)(X + base);
    const float* s1 = g_s1 + bg * cout + c;
    const float* s2 = g_s2 + bg * cout + c;
    float r[4] = {v.x, v.y, v.z, v.w};
#pragma unroll
    for (int i = 0; i < 4; i++) {
        float t = s2[i] * (r[i] - s1[i]) + b[c + i];
        r[i] = (t >= 0.f) ? t : 0.2f * t;
    }
    *(float4*)(X + base) = make_float4(r[0], r[1], r[2], r[3]);
    if (abf) {
        __half2* ph = (__half2*)(abf + (size_t)n * astr + c);
        ph[0] = __floats2half2_rn(r[0], r[1]);
        ph[1] = __floats2half2_rn(r[2], r[3]);
    }
}

// ---------------- residual + mean pool ----------------
__global__ void k_pool(const float* __restrict__ h, const float* __restrict__ x) {
    int bg = blockIdx.x;
    int c = threadIdx.x;  // 128
    int s = g_ptr[bg];
    int e = g_ptr[bg + 1];
    float sa = 0.f, sb = 0.f, sc = 0.f, sd = 0.f;
    int n = s;
    for (; n + 4 <= e; n += 4) {
        sa += h[(size_t)n * 128 + c] + x[(size_t)n * 128 + c];
        sb += h[(size_t)(n + 1) * 128 + c] + x[(size_t)(n + 1) * 128 + c];
        sc += h[(size_t)(n + 2) * 128 + c] + x[(size_t)(n + 2) * 128 + c];
        sd += h[(size_t)(n + 3) * 128 + c] + x[(size_t)(n + 3) * 128 + c];
    }
    for (; n < e; n++) sa += h[(size_t)n * 128 + c] + x[(size_t)n * 128 + c];
    g_pool[bg * 128 + c] = ((sa + sb) + (sc + sd)) / g_cnt[bg];
}

// ---------------- MLP head ----------------
__global__ void k_head(const float* __restrict__ W1, const float* __restrict__ b1,
                       const float* __restrict__ W2, const float* __restrict__ b2,
                       float* __restrict__ out) {
    int bg = blockIdx.x;
    __shared__ float hid[64];
    int j = threadIdx.x;  // 64
    float s = b1[j];
    for (int i = 0; i < 128; i++) s += g_pool[bg * 128 + i] * W1[i * 64 + j];
    hid[j] = tanhf(s);
    __syncthreads();
    if (j < 10) {
        float o = b2[j];
        for (int i = 0; i < 64; i++) o += hid[i] * W2[i * 10 + j];
        out[bg * 10 + j] = o;
    }
}

// ---------------- host orchestration ----------------
static void prop_launch(int nch, const __half* hsrc, int hstr, int hoff,
                        const __half* b1, int b1str, float c1,
                        const __half* b2, int b2str, float c2,
                        const float* bias, float scale,
                        float* out, int ostr,
                        __half* abf, int aoff, int astr) {
    if (nch == 128) {
        k_prop<128, 8><<<NN / 8, dim3(16, 8)>>>(hsrc, hstr, hoff, b1, b1str, c1,
                                                b2, b2str, c2, bias, scale,
                                                out, ostr, abf, aoff, astr);
    } else {
        k_prop<256, 4><<<NN / 4, dim3(32, 4)>>>(hsrc, hstr, hoff, b1, b1str, c1,
                                                b2, b2str, c2, bias, scale,
                                                out, ostr, abf, aoff, astr);
    }
}

static void gn_launch(float* X, const float* w, const float* b, const float* ms,
                      const int* batch, int cout, int lc, __half* abf, int astr) {
    k_gnzero<<<cdiv(BB * cout, 256), 256>>>(cout);
    dim3 gs(BB, cout / 128, GN_CHK);
    k_gnstat<<<gs, 128>>>(X, cout);
    k_gnfin<<<cdiv(BB * cout, 256), 256>>>(w, ms, cout);
    k_gnnorm<<<cdiv(NN * cout / 4, 256), 256>>>(X, b, batch, cout, lc, abf, astr);
}

extern "C" void kernel_launch(void* const* d_in, const int* in_sizes, int n_in,
                              void* d_out, int out_size) {
    const float* x = (const float*)d_in[0];
    const int* ei = (const int*)d_in[1];
    const int* src = ei;
    const int* dst = ei + EE;
    const int* batch = (const int*)d_in[2];

    float *f0, *f1;
    __half *abf, *cbf, *ubf;
    cudaGetSymbolAddress((void**)&f0, g_f0);
    cudaGetSymbolAddress((void**)&f1, g_f1);
    cudaGetSymbolAddress((void**)&abf, g_abf);
    cudaGetSymbolAddress((void**)&cbf, g_cbf);
    cudaGetSymbolAddress((void**)&ubf, g_ubf);

    // ---- setup: degrees, CSR, graph segments ----
    k_zero_deg<<<cdiv(NN, 256), 256>>>();
    k_deg<<<cdiv(EE, 256), 256>>>(dst);
    k_dinv<<<cdiv(NN, 256), 256>>>();
    k_scan1<<<SCAN_BLK, 256>>>();
    k_scan2<<<1, 32>>>();
    k_scan3<<<SCAN_BLK, 256>>>();
    k_fill<<<cdiv(EE, 256), 256>>>(src, dst);
    k_ptr<<<cdiv(NN, 256), 256>>>(batch);
    k_cnt<<<1, 64>>>();

    // ================= Layer 1 (mode A, 128 -> 256, K = 384) =================
    {
        const int cin = 128, cout = 256, K = 3 * cin;
        k_convAx<<<cdiv(NN * 128, 256), 256>>>(x);
        // t1 = prop(x)
        prop_launch(cin, abf, K, 0, nullptr, 0, 0.f, nullptr, 0, 0.f, nullptr, 1.0f,
                    nullptr, 0, abf, cin, K);
        // t2 = 2*prop(t1) - x  (x correction read fp16 from abf[0])
        prop_launch(cin, abf, K, cin, abf, K, -1.0f, nullptr, 0, 0.f, nullptr, 2.0f,
                    nullptr, 0, abf, 2 * cin, K);
        k_convW<<<cdiv(cout * K, 256), 256>>>((const float*)d_in[3], cin, cout);
        dim3 gg(MPAD / 128, cout / 128);
        k_gemm_mma<<<gg, 256>>>((const float*)d_in[4], f0, nullptr, K, cout);
        gn_launch(f0, (const float*)d_in[5], (const float*)d_in[6],
                  (const float*)d_in[7], batch, cout, 8, abf, 3 * 256);
    }

    // ================= Layer 2 (mode A, 256 -> 512, K = 768) =================
    {
        const int cin = 256, cout = 512, K = 3 * cin;
        prop_launch(cin, abf, K, 0, nullptr, 0, 0.f, nullptr, 0, 0.f, nullptr, 1.0f,
                    nullptr, 0, abf, cin, K);
        prop_launch(cin, abf, K, cin, abf, K, -1.0f, nullptr, 0, 0.f, nullptr, 2.0f,
                    nullptr, 0, abf, 2 * cin, K);
        k_convW<<<cdiv(cout * K, 256), 256>>>((const float*)d_in[8], cin, cout);
        dim3 gg(MPAD / 128, cout / 128);
        k_gemm_mma<<<gg, 256>>>((const float*)d_in[9], f1, nullptr, K, cout);
        gn_launch(f1, (const float*)d_in[10], (const float*)d_in[11],
                  (const float*)d_in[12], batch, cout, 9, abf, 512);
    }

    // ================= Layer 3 (mode B, 512 -> 256, K = 512) =================
    {
        const int cin = 512, cout = 256;
        k_convWB<<<cdiv(3 * cout * cin, 256), 256>>>((const float*)d_in[13], cin, cout);
        dim3 gg(MPAD / 128, (3 * cout) / 128);
        k_gemm_mma<<<gg, 256>>>(nullptr, nullptr, cbf, cin, 3 * cout);  // cbf=[P0|P1|P2] fp16
        // u = P1 + 2*prop(P2)
        prop_launch(cout, cbf, 3 * cout, 2 * cout, cbf + cout, 3 * cout, 1.0f,
                    nullptr, 0, 0.f, nullptr, 2.0f, nullptr, 0, ubf, 0, cout);
        // out = prop(u) + P0 - P2 + bias
        prop_launch(cout, ubf, cout, 0, cbf, 3 * cout, 1.0f, cbf + 2 * cout, 3 * cout, -1.0f,
                    (const float*)d_in[14], 1.0f, f0, cout, nullptr, 0, 0);
        gn_launch(f0, (const float*)d_in[15], (const float*)d_in[16],
                  (const float*)d_in[17], batch, cout, 8, abf, 256);
    }

    // ================= Layer 4 (mode B, 256 -> 128, K = 256) =================
    {
        const int cin = 256, cout = 128;
        k_convWB<<<cdiv(3 * cout * cin, 256), 256>>>((const float*)d_in[18], cin, cout);
        dim3 gg(MPAD / 128, (3 * cout) / 128);
        k_gemm_mma<<<gg, 256>>>(nullptr, nullptr, cbf, cin, 3 * cout);
        prop_launch(cout, cbf, 3 * cout, 2 * cout, cbf + cout, 3 * cout, 1.0f,
                    nullptr, 0, 0.f, nullptr, 2.0f, nullptr, 0, ubf, 0, cout);
        prop_launch(cout, ubf, cout, 0, cbf, 3 * cout, 1.0f, cbf + 2 * cout, 3 * cout, -1.0f,
                    (const float*)d_in[19], 1.0f, f1, cout, nullptr, 0, 0);
        gn_launch(f1, (const float*)d_in[20], (const float*)d_in[21],
                  (const float*)d_in[22], batch, cout, 7, nullptr, 0);
    }

    // ---- residual + pool + head ----
    k_pool<<<BB, 128>>>(f1, x);
    k_head<<<BB, 64>>>((const float*)d_in[23], (const float*)d_in[24],
                       (const float*)d_in[25], (const float*)d_in[26],
                       (float*)d_out);
}

// round 15
// speedup vs baseline: 1.1010x; 1.0141x over previous
#include <cuda_runtime.h>
#include <cuda_fp16.h>
#include <math.h>
#include <cstdint>

#define NN 50000
#define EE 800000
#define BB 50
#define GN_EPS 1e-5f
#define MPAD 50048   // 391 * 128
#define SCAN_BLK 49  // ceil(NN / 1024)
#define GN_CHK 8

// ---------------- scratch (static device memory; no allocations) ----------------
__device__ float g_f0[(size_t)NN * 512];
__device__ float g_f1[(size_t)NN * 512];
__device__ __half g_abf[(size_t)MPAD * 1536];   // fp16 A; pad rows read-only garbage (discarded)
__device__ __half g_wbf[(size_t)512 * 2304];    // fp16 W (n-major)
__device__ __half g_cbf[(size_t)NN * 768];      // fp16 [P0|P1|P2] (mode B)
__device__ __half g_ubf[(size_t)NN * 256];      // fp16 u (mode B)
__device__ float g_s1[BB * 512];
__device__ float g_s2[BB * 512];
__device__ int   g_deg[NN];
__device__ int   g_off[NN + 1];
__device__ int   g_fill[NN];
__device__ int   g_bsum[SCAN_BLK];
__device__ int   g_boff[SCAN_BLK];
__device__ int2  g_srcw[EE];   // {src, float_bits(w)}
__device__ int   g_ptr[BB + 1];
__device__ float g_cnt[BB];
__device__ float g_pool[BB * 128];

static inline int cdiv(int a, int b) { return (a + b - 1) / b; }

// ---------------- PTX helpers ----------------
__device__ __forceinline__ uint32_t smem_u32(const void* p) {
    uint32_t a;
    asm("{ .reg .u64 t; cvta.to.shared.u64 t, %1; cvt.u32.u64 %0, t; }" : "=r"(a) : "l"(p));
    return a;
}

__device__ __forceinline__ void cp_async16(uint32_t dst, const void* src) {
    asm volatile("cp.async.cg.shared.global [%0], [%1], 16;\n" :: "r"(dst), "l"(src));
}
#define CP_COMMIT() asm volatile("cp.async.commit_group;\n" ::: "memory")
#define CP_WAIT(n)  asm volatile("cp.async.wait_group %0;\n" :: "n"(n) : "memory")

__device__ __forceinline__ void mma_f16(float* c, uint32_t a0, uint32_t a1, uint32_t a2,
                                        uint32_t a3, uint32_t b0, uint32_t b1) {
    asm volatile(
        "mma.sync.aligned.m16n8k16.row.col.f32.f16.f16.f32 "
        "{%0,%1,%2,%3}, {%4,%5,%6,%7}, {%8,%9}, {%0,%1,%2,%3};"
        : "+f"(c[0]), "+f"(c[1]), "+f"(c[2]), "+f"(c[3])
        : "r"(a0), "r"(a1), "r"(a2), "r"(a3), "r"(b0), "r"(b1));
}

__device__ __forceinline__ void ldsm_x4(uint32_t& r0, uint32_t& r1, uint32_t& r2,
                                        uint32_t& r3, uint32_t addr) {
    asm volatile("ldmatrix.sync.aligned.m8n8.x4.shared.b16 {%0,%1,%2,%3}, [%4];"
                 : "=r"(r0), "=r"(r1), "=r"(r2), "=r"(r3) : "r"(addr));
}

// fma of 8 fp16 channels (raw uint4) into 8 fp32 accumulators
__device__ __forceinline__ void fma8(float* acc, float w, const uint4& raw) {
    const __half2* hp = (const __half2*)&raw;
#pragma unroll
    for (int i = 0; i < 4; i++) {
        float2 v = __half22float2(hp[i]);
        acc[2 * i] = fmaf(w, v.x, acc[2 * i]);
        acc[2 * i + 1] = fmaf(w, v.y, acc[2 * i + 1]);
    }
}

// ---------------- setup kernels ----------------
__global__ void k_zero_deg() {
    int i = blockIdx.x * blockDim.x + threadIdx.x;
    if (i < NN) g_deg[i] = 0;
}

__global__ void k_deg(const int* __restrict__ dst) {
    int e = blockIdx.x * blockDim.x + threadIdx.x;
    if (e < EE) atomicAdd(&g_deg[dst[e]], 1);
}

// ---- 3-phase scan ----
__global__ void k_scan1() {
    __shared__ int red[256];
    int b = blockIdx.x;
    int t = threadIdx.x;
    int base = b * 1024 + t * 4;
    int s = 0;
#pragma unroll
    for (int i = 0; i < 4; i++) {
        int idx = base + i;
        if (idx < NN) s += g_deg[idx];
    }
    red[t] = s;
    __syncthreads();
    for (int off = 128; off > 0; off >>= 1) {
        if (t < off) red[t] += red[t + off];
        __syncthreads();
    }
    if (t == 0) g_bsum[b] = red[0];
}

__global__ void k_scan2() {
    if (threadIdx.x == 0) {
        int acc = 0;
        for (int i = 0; i < SCAN_BLK; i++) {
            g_boff[i] = acc;
            acc += g_bsum[i];
        }
        g_off[NN] = acc;
    }
}

__global__ void k_scan3() {
    __shared__ int pre[256];
    int b = blockIdx.x;
    int t = threadIdx.x;
    int base = b * 1024 + t * 4;
    int d[4];
    int s = 0;
#pragma unroll
    for (int i = 0; i < 4; i++) {
        int idx = base + i;
        d[i] = (idx < NN) ? g_deg[idx] : 0;
        s += d[i];
    }
    pre[t] = s;
    __syncthreads();
    for (int off = 1; off < 256; off <<= 1) {
        int v = (t >= off) ? pre[t - off] : 0;
        __syncthreads();
        pre[t] += v;
        __syncthreads();
    }
    int run = g_boff[b] + pre[t] - s;
#pragma unroll
    for (int i = 0; i < 4; i++) {
        int idx = base + i;
        if (idx < NN) {
            g_off[idx] = run;
            g_fill[idx] = run;
            run += d[i];
        }
    }
}

// fill CSR; weight computed inline from degrees (dinv fused)
__global__ void k_fill(const int* __restrict__ src, const int* __restrict__ dst) {
    int e = blockIdx.x * blockDim.x + threadIdx.x;
    if (e < EE) {
        int d = dst[e];
        int s = src[e];
        int pos = atomicAdd(&g_fill[d], 1);
        int ds = g_deg[s];
        int dd = g_deg[d];
        float w = (ds > 0) ? -rsqrtf((float)ds) * rsqrtf((float)dd) : 0.0f;
        g_srcw[pos] = make_int2(s, __float_as_int(w));
    }
}

__global__ void k_ptr(const int* __restrict__ batch) {
    int n = blockIdx.x * blockDim.x + threadIdx.x;
    if (n >= NN) return;
    int b = batch[n];
    if (n == 0) {
        for (int bb = 0; bb <= b; bb++) g_ptr[bb] = 0;
    } else {
        int pb = batch[n - 1];
        for (int bb = pb + 1; bb <= b; bb++) g_ptr[bb] = n;
    }
    if (n == NN - 1) {
        for (int bb = b + 1; bb <= BB; bb++) g_ptr[bb] = NN;
    }
}

__global__ void k_cnt() {
    int b = threadIdx.x;
    if (b < BB) {
        int c = g_ptr[b + 1] - g_ptr[b];
        g_cnt[b] = (c > 0) ? (float)c : 1.0f;
    }
}

// ---------------- propagation: 16B fp16 gathers, 8 channels/thread ----------------
template <int NCH, int NPB>
__global__ void __launch_bounds__((NCH / 8) * NPB) k_prop(
    const __half* __restrict__ hsrc, int hstr, int hoff,
    const __half* __restrict__ b1, int b1str, float c1,
    const __half* __restrict__ b2, int b2str, float c2,
    const float* __restrict__ bias, float scale,
    float* __restrict__ out, int ostr,
    __half* abf, int aoff, int astr) {
    int n = blockIdx.x * NPB + threadIdx.y;
    int c = threadIdx.x * 8;
    int s = g_off[n], e = g_off[n + 1];
    const __half* hb = hsrc + hoff + c;
    float a0[8] = {}, a1[8] = {};
    int ed = s;
    for (; ed + 4 <= e; ed += 4) {
        int2 p0 = g_srcw[ed], p1 = g_srcw[ed + 1], p2 = g_srcw[ed + 2], p3 = g_srcw[ed + 3];
        uint4 r0 = *(const uint4*)(hb + (size_t)p0.x * hstr);
        uint4 r1 = *(const uint4*)(hb + (size_t)p1.x * hstr);
        uint4 r2 = *(const uint4*)(hb + (size_t)p2.x * hstr);
        uint4 r3 = *(const uint4*)(hb + (size_t)p3.x * hstr);
        fma8(a0, __int_as_float(p0.y), r0);
        fma8(a1, __int_as_float(p1.y), r1);
        fma8(a0, __int_as_float(p2.y), r2);
        fma8(a1, __int_as_float(p3.y), r3);
    }
    for (; ed < e; ed++) {
        int2 p = g_srcw[ed];
        uint4 r = *(const uint4*)(hb + (size_t)p.x * hstr);
        fma8(a0, __int_as_float(p.y), r);
    }
    float r[8];
#pragma unroll
    for (int i = 0; i < 8; i++) r[i] = (a0[i] + a1[i]) * scale;
    if (b1) {
        uint4 raw = *(const uint4*)(b1 + (size_t)n * b1str + c);
        const __half2* hp = (const __half2*)&raw;
#pragma unroll
        for (int i = 0; i < 4; i++) {
            float2 v = __half22float2(hp[i]);
            r[2 * i] += c1 * v.x;
            r[2 * i + 1] += c1 * v.y;
        }
    }
    if (b2) {
        uint4 raw = *(const uint4*)(b2 + (size_t)n * b2str + c);
        const __half2* hp = (const __half2*)&raw;
#pragma unroll
        for (int i = 0; i < 4; i++) {
            float2 v = __half22float2(hp[i]);
            r[2 * i] += c2 * v.x;
            r[2 * i + 1] += c2 * v.y;
        }
    }
    if (bias) {
#pragma unroll
        for (int i = 0; i < 8; i++) r[i] += __ldg(bias + c + i);
    }
    if (out) {
        *(float4*)(out + (size_t)n * ostr + c) = make_float4(r[0], r[1], r[2], r[3]);
        *(float4*)(out + (size_t)n * ostr + c + 4) = make_float4(r[4], r[5], r[6], r[7]);
    }
    if (abf) {
        __half2 ov[4];
#pragma unroll
        for (int i = 0; i < 4; i++) ov[i] = __floats2half2_rn(r[2 * i], r[2 * i + 1]);
        *(uint4*)(abf + (size_t)n * astr + aoff + c) = *(uint4*)ov;
    }
}

// ---------------- fp16 convert of x ----------------
__global__ void k_convAx(const float* __restrict__ x) {
    int idx = blockIdx.x * blockDim.x + threadIdx.x;
    if (idx >= NN * 128) return;
    int n = idx >> 7;
    int c = idx & 127;
    g_abf[(size_t)n * 384 + c] = __float2half_rn(x[idx]);
}

// ---------------- weight converts ----------------
__global__ void k_convW(const float* __restrict__ W, int cin, int cout) {
    int K3 = 3 * cin;
    int idx = blockIdx.x * blockDim.x + threadIdx.x;
    if (idx >= cout * K3) return;
    int n = idx / K3;
    int R = idx - n * K3;
    g_wbf[(size_t)n * K3 + R] = __float2half_rn(W[(size_t)R * cout + n]);
}

__global__ void k_convWB(const float* __restrict__ W, int cin, int cout) {
    int idx = blockIdx.x * blockDim.x + threadIdx.x;
    if (idx >= 3 * cout * cin) return;
    int n = idx / cin;
    int k = idx - n * cin;
    int j = n / cout;
    int nc = n - j * cout;
    g_wbf[(size_t)n * cin + k] = __float2half_rn(W[((size_t)j * cin + k) * cout + nc]);
}

// ---------------- tensor-core GEMM: mma.sync + ldmatrix, 3-stage cp.async pipeline ----------------
#define BM 128
#define BN 128
#define BK 32
#define ASTR 40

__global__ void __launch_bounds__(256)
k_gemm_mma(const float* __restrict__ bias, float* __restrict__ C,
           __half* __restrict__ Ch, int K, int Ncols) {
    __shared__ __align__(16) __half As[3][BM * ASTR];
    __shared__ __align__(16) __half Bs[3][BN * ASTR];
    int tid = threadIdx.x;
    int lane = tid & 31;
    int wid = tid >> 5;
    int wm = wid >> 2;
    int wn = wid & 3;
    int m0 = blockIdx.x * BM;
    int n0 = blockIdx.y * BN;
    int nch = K / BK;

    float c[4][4][4] = {};

    int lrow = tid >> 2;
    int lcol = (tid & 3) * 8;
    uint32_t sa = smem_u32(As);
    uint32_t sb = smem_u32(Bs);
    uint32_t dstA = sa + (uint32_t)(lrow * ASTR + lcol) * 2;
    uint32_t dstB = sb + (uint32_t)(lrow * ASTR + lcol) * 2;
    const uint32_t bufsz = (uint32_t)BM * ASTR * 2;

    int qr = lane >> 2;
    int qc = (lane & 3) * 2;

    uint32_t a_off = (uint32_t)((wm * 64 + (lane & 15)) * ASTR + (lane >> 4) * 8) * 2;
    int bg_ = lane >> 3;
    uint32_t b_off = (uint32_t)((wn * 32 + (bg_ >> 1) * 8 + (lane & 7)) * ASTR
                                + (bg_ & 1) * 8) * 2;

    const __half* agb = g_abf + (size_t)(m0 + lrow) * K + lcol;
    const __half* bgb = g_wbf + (size_t)(n0 + lrow) * K + lcol;

    // prefetch chunks 0, 1 into buffers 0, 1
#pragma unroll
    for (int pf = 0; pf < 2; pf++) {
        if (pf < nch) {
            int kg = pf * BK;
            uint32_t da = dstA + pf * bufsz;
            uint32_t db = dstB + pf * bufsz;
            cp_async16(da, agb + kg);
            cp_async16(da + 64u * ASTR * 2, agb + kg + (size_t)64 * K);
            cp_async16(db, bgb + kg);
            cp_async16(db + 64u * ASTR * 2, bgb + kg + (size_t)64 * K);
            CP_COMMIT();
        }
    }

    int buf = 0;
    for (int ch = 0; ch < nch; ch++) {
        if (ch + 2 < nch) {
            int kg = (ch + 2) * BK;
            int pbuf = (buf + 2 >= 3) ? buf - 1 : buf + 2;
            uint32_t da = dstA + pbuf * bufsz;
            uint32_t db = dstB + pbuf * bufsz;
            cp_async16(da, agb + kg);
            cp_async16(da + 64u * ASTR * 2, agb + kg + (size_t)64 * K);
            cp_async16(db, bgb + kg);
            cp_async16(db + 64u * ASTR * 2, bgb + kg + (size_t)64 * K);
            CP_COMMIT();
            CP_WAIT(2);
        } else if (ch + 1 < nch) {
            CP_WAIT(1);
        } else {
            CP_WAIT(0);
        }
        __syncthreads();

        uint32_t abase = sa + buf * bufsz + a_off;
        uint32_t bbase = sb + buf * bufsz + b_off;
#pragma unroll
        for (int ks = 0; ks < 2; ks++) {
            uint32_t kso = (uint32_t)(ks * 16) * 2;
            uint32_t a[4][4];
#pragma unroll
            for (int mi = 0; mi < 4; mi++)
                ldsm_x4(a[mi][0], a[mi][1], a[mi][2], a[mi][3],
                        abase + kso + (uint32_t)(mi * 16 * ASTR) * 2);
            uint32_t b[4][2];
#pragma unroll
            for (int nj = 0; nj < 2; nj++)
                ldsm_x4(b[nj * 2][0], b[nj * 2][1], b[nj * 2 + 1][0], b[nj * 2 + 1][1],
                        bbase + kso + (uint32_t)(nj * 16 * ASTR) * 2);
#pragma unroll
            for (int mi = 0; mi < 4; mi++)
#pragma unroll
                for (int ni = 0; ni < 4; ni++)
                    mma_f16(c[mi][ni], a[mi][0], a[mi][1], a[mi][2], a[mi][3],
                            b[ni][0], b[ni][1]);
        }
        __syncthreads();
        buf = (buf + 1 >= 3) ? 0 : buf + 1;
    }

    float bv0[4], bv1[4];
#pragma unroll
    for (int ni = 0; ni < 4; ni++) {
        int col = n0 + wn * 32 + ni * 8 + qc;
        bv0[ni] = bias ? bias[col] : 0.0f;
        bv1[ni] = bias ? bias[col + 1] : 0.0f;
    }
#pragma unroll
    for (int mi = 0; mi < 4; mi++) {
        int r = m0 + wm * 64 + mi * 16 + qr;
#pragma unroll
        for (int ni = 0; ni < 4; ni++) {
            int col = n0 + wn * 32 + ni * 8 + qc;
            if (r < NN) {
                float va = c[mi][ni][0] + bv0[ni];
                float vb = c[mi][ni][1] + bv1[ni];
                if (C) *(float2*)&C[(size_t)r * Ncols + col] = make_float2(va, vb);
                if (Ch) *(__half2*)&Ch[(size_t)r * Ncols + col] = __floats2half2_rn(va, vb);
            }
            if (r + 8 < NN) {
                float va = c[mi][ni][2] + bv0[ni];
                float vb = c[mi][ni][3] + bv1[ni];
                if (C) *(float2*)&C[(size_t)(r + 8) * Ncols + col] = make_float2(va, vb);
                if (Ch) *(__half2*)&Ch[(size_t)(r + 8) * Ncols + col] = __floats2half2_rn(va, vb);
            }
        }
    }
}

// ---------------- GraphNorm: chip-wide 4-phase ----------------
__global__ void k_gnzero(int cout) {
    int idx = blockIdx.x * blockDim.x + threadIdx.x;
    if (idx < BB * cout) {
        g_s1[idx] = 0.f;
        g_s2[idx] = 0.f;
    }
}

__global__ void k_gnstat(const float* __restrict__ X, int cout) {
    int bg = blockIdx.x;
    int ci = threadIdx.x;
    int c = blockIdx.y * 128 + ci;
    int s = g_ptr[bg], e = g_ptr[bg + 1];
    int len = e - s;
    int chunk = (len + GN_CHK - 1) / GN_CHK;
    int ns = s + blockIdx.z * chunk;
    int ne = min(ns + chunk, e);
    float s1 = 0.f, s2 = 0.f;
    for (int n = ns; n < ne; n++) {
        float v = X[(size_t)n * cout + c];
        s1 += v;
        s2 = fmaf(v, v, s2);
    }
    if (ns < ne) {
        atomicAdd(&g_s1[bg * cout + c], s1);
        atomicAdd(&g_s2[bg * cout + c], s2);
    }
}

__global__ void k_gnfin(const float* __restrict__ w, const float* __restrict__ ms,
                        int cout) {
    int idx = blockIdx.x * blockDim.x + threadIdx.x;
    if (idx >= BB * cout) return;
    int bg = idx / cout;
    int c = idx - bg * cout;
    float invc = 1.0f / g_cnt[bg];
    float mean = g_s1[idx] * invc;
    float m = ms[c] * mean;
    float var = fmaxf(g_s2[idx] * invc - 2.0f * m * mean + m * m, 0.0f);
    g_s1[idx] = m;
    g_s2[idx] = w[c] * rsqrtf(var + GN_EPS);
}

// elementwise normalize + leaky relu; optional fp32 writeback + optional fp16 write
__global__ void k_gnnorm(const float* __restrict__ X, float* __restrict__ Xout,
                         const float* __restrict__ b,
                         const int* __restrict__ batch, int cout, int lc,
                         __half* abf, int astr) {
    int idx = blockIdx.x * blockDim.x + threadIdx.x;
    int base = idx * 4;
    if (base >= NN * cout) return;
    int n = base >> lc;
    int c = base & (cout - 1);
    int bg = batch[n];
    float4 v = *(const float4*)(X + base);
    const float* s1 = g_s1 + bg * cout + c;
    const float* s2 = g_s2 + bg * cout + c;
    float r[4] = {v.x, v.y, v.z, v.w};
#pragma unroll
    for (int i = 0; i < 4; i++) {
        float t = s2[i] * (r[i] - s1[i]) + b[c + i];
        r[i] = (t >= 0.f) ? t : 0.2f * t;
    }
    if (Xout) *(float4*)(Xout + base) = make_float4(r[0], r[1], r[2], r[3]);
    if (abf) {
        __half2* ph = (__half2*)(abf + (size_t)n * astr + c);
        ph[0] = __floats2half2_rn(r[0], r[1]);
        ph[1] = __floats2half2_rn(r[2], r[3]);
    }
}

// ---------------- residual + mean pool ----------------
__global__ void k_pool(const float* __restrict__ h, const float* __restrict__ x) {
    int bg = blockIdx.x;
    int c = threadIdx.x;  // 128
    int s = g_ptr[bg];
    int e = g_ptr[bg + 1];
    float sa = 0.f, sb = 0.f, sc = 0.f, sd = 0.f;
    int n = s;
    for (; n + 4 <= e; n += 4) {
        sa += h[(size_t)n * 128 + c] + x[(size_t)n * 128 + c];
        sb += h[(size_t)(n + 1) * 128 + c] + x[(size_t)(n + 1) * 128 + c];
        sc += h[(size_t)(n + 2) * 128 + c] + x[(size_t)(n + 2) * 128 + c];
        sd += h[(size_t)(n + 3) * 128 + c] + x[(size_t)(n + 3) * 128 + c];
    }
    for (; n < e; n++) sa += h[(size_t)n * 128 + c] + x[(size_t)n * 128 + c];
    g_pool[bg * 128 + c] = ((sa + sb) + (sc + sd)) / g_cnt[bg];
}

// ---------------- MLP head ----------------
__global__ void k_head(const float* __restrict__ W1, const float* __restrict__ b1,
                       const float* __restrict__ W2, const float* __restrict__ b2,
                       float* __restrict__ out) {
    int bg = blockIdx.x;
    __shared__ float hid[64];
    int j = threadIdx.x;  // 64
    float s = b1[j];
    for (int i = 0; i < 128; i++) s += g_pool[bg * 128 + i] * W1[i * 64 + j];
    hid[j] = tanhf(s);
    __syncthreads();
    if (j < 10) {
        float o = b2[j];
        for (int i = 0; i < 64; i++) o += hid[i] * W2[i * 10 + j];
        out[bg * 10 + j] = o;
    }
}

// ---------------- host orchestration ----------------
static void prop_launch(int nch, const __half* hsrc, int hstr, int hoff,
                        const __half* b1, int b1str, float c1,
                        const __half* b2, int b2str, float c2,
                        const float* bias, float scale,
                        float* out, int ostr,
                        __half* abf, int aoff, int astr) {
    if (nch == 128) {
        k_prop<128, 8><<<NN / 8, dim3(16, 8)>>>(hsrc, hstr, hoff, b1, b1str, c1,
                                                b2, b2str, c2, bias, scale,
                                                out, ostr, abf, aoff, astr);
    } else {
        k_prop<256, 4><<<NN / 4, dim3(32, 4)>>>(hsrc, hstr, hoff, b1, b1str, c1,
                                                b2, b2str, c2, bias, scale,
                                                out, ostr, abf, aoff, astr);
    }
}

static void gn_launch(const float* X, float* Xout, const float* w, const float* b,
                      const float* ms, const int* batch, int cout, int lc,
                      __half* abf, int astr) {
    k_gnzero<<<cdiv(BB * cout, 256), 256>>>(cout);
    dim3 gs(BB, cout / 128, GN_CHK);
    k_gnstat<<<gs, 128>>>(X, cout);
    k_gnfin<<<cdiv(BB * cout, 256), 256>>>(w, ms, cout);
    k_gnnorm<<<cdiv(NN * cout / 4, 256), 256>>>(X, Xout, b, batch, cout, lc, abf, astr);
}

extern "C" void kernel_launch(void* const* d_in, const int* in_sizes, int n_in,
                              void* d_out, int out_size) {
    const float* x = (const float*)d_in[0];
    const int* ei = (const int*)d_in[1];
    const int* src = ei;
    const int* dst = ei + EE;
    const int* batch = (const int*)d_in[2];

    float *f0, *f1;
    __half *abf, *cbf, *ubf;
    cudaGetSymbolAddress((void**)&f0, g_f0);
    cudaGetSymbolAddress((void**)&f1, g_f1);
    cudaGetSymbolAddress((void**)&abf, g_abf);
    cudaGetSymbolAddress((void**)&cbf, g_cbf);
    cudaGetSymbolAddress((void**)&ubf, g_ubf);

    // ---- setup: degrees, CSR, graph segments ----
    k_zero_deg<<<cdiv(NN, 256), 256>>>();
    k_deg<<<cdiv(EE, 256), 256>>>(dst);
    k_scan1<<<SCAN_BLK, 256>>>();
    k_scan2<<<1, 32>>>();
    k_scan3<<<SCAN_BLK, 256>>>();
    k_fill<<<cdiv(EE, 256), 256>>>(src, dst);
    k_ptr<<<cdiv(NN, 256), 256>>>(batch);
    k_cnt<<<1, 64>>>();

    // ================= Layer 1 (mode A, 128 -> 256, K = 384) =================
    {
        const int cin = 128, cout = 256, K = 3 * cin;
        k_convAx<<<cdiv(NN * 128, 256), 256>>>(x);
        prop_launch(cin, abf, K, 0, nullptr, 0, 0.f, nullptr, 0, 0.f, nullptr, 1.0f,
                    nullptr, 0, abf, cin, K);
        prop_launch(cin, abf, K, cin, abf, K, -1.0f, nullptr, 0, 0.f, nullptr, 2.0f,
                    nullptr, 0, abf, 2 * cin, K);
        k_convW<<<cdiv(cout * K, 256), 256>>>((const float*)d_in[3], cin, cout);
        dim3 gg(MPAD / 128, cout / 128);
        k_gemm_mma<<<gg, 256>>>((const float*)d_in[4], f0, nullptr, K, cout);
        gn_launch(f0, nullptr, (const float*)d_in[5], (const float*)d_in[6],
                  (const float*)d_in[7], batch, cout, 8, abf, 3 * 256);
    }

    // ================= Layer 2 (mode A, 256 -> 512, K = 768) =================
    {
        const int cin = 256, cout = 512, K = 3 * cin;
        prop_launch(cin, abf, K, 0, nullptr, 0, 0.f, nullptr, 0, 0.f, nullptr, 1.0f,
                    nullptr, 0, abf, cin, K);
        prop_launch(cin, abf, K, cin, abf, K, -1.0f, nullptr, 0, 0.f, nullptr, 2.0f,
                    nullptr, 0, abf, 2 * cin, K);
        k_convW<<<cdiv(cout * K, 256), 256>>>((const float*)d_in[8], cin, cout);
        dim3 gg(MPAD / 128, cout / 128);
        k_gemm_mma<<<gg, 256>>>((const float*)d_in[9], f1, nullptr, K, cout);
        gn_launch(f1, nullptr, (const float*)d_in[10], (const float*)d_in[11],
                  (const float*)d_in[12], batch, cout, 9, abf, 512);
    }

    // ================= Layer 3 (mode B, 512 -> 256, K = 512) =================
    {
        const int cin = 512, cout = 256;
        k_convWB<<<cdiv(3 * cout * cin, 256), 256>>>((const float*)d_in[13], cin, cout);
        dim3 gg(MPAD / 128, (3 * cout) / 128);
        k_gemm_mma<<<gg, 256>>>(nullptr, nullptr, cbf, cin, 3 * cout);  // cbf=[P0|P1|P2] fp16
        prop_launch(cout, cbf, 3 * cout, 2 * cout, cbf + cout, 3 * cout, 1.0f,
                    nullptr, 0, 0.f, nullptr, 2.0f, nullptr, 0, ubf, 0, cout);
        prop_launch(cout, ubf, cout, 0, cbf, 3 * cout, 1.0f, cbf + 2 * cout, 3 * cout, -1.0f,
                    (const float*)d_in[14], 1.0f, f0, cout, nullptr, 0, 0);
        gn_launch(f0, nullptr, (const float*)d_in[15], (const float*)d_in[16],
                  (const float*)d_in[17], batch, cout, 8, abf, 256);
    }

    // ================= Layer 4 (mode B, 256 -> 128, K = 256) =================
    {
        const int cin = 256, cout = 128;
        k_convWB<<<cdiv(3 * cout * cin, 256), 256>>>((const float*)d_in[18], cin, cout);
        dim3 gg(MPAD / 128, (3 * cout) / 128);
        k_gemm_mma<<<gg, 256>>>(nullptr, nullptr, cbf, cin, 3 * cout);
        prop_launch(cout, cbf, 3 * cout, 2 * cout, cbf + cout, 3 * cout, 1.0f,
                    nullptr, 0, 0.f, nullptr, 2.0f, nullptr, 0, ubf, 0, cout);
        prop_launch(cout, ubf, cout, 0, cbf, 3 * cout, 1.0f, cbf + 2 * cout, 3 * cout, -1.0f,
                    (const float*)d_in[19], 1.0f, f1, cout, nullptr, 0, 0);
        // layer 4: keep fp32 writeback (k_pool reads it)
        gn_launch(f1, f1, (const float*)d_in[20], (const float*)d_in[21],
                  (const float*)d_in[22], batch, cout, 7, nullptr, 0);
    }

    // ---- residual + pool + head ----
    k_pool<<<BB, 128>>>(f1, x);
    k_head<<<BB, 64>>>((const float*)d_in[23], (const float*)d_in[24],
                       (const float*)d_in[25], (const float*)d_in[26],
                       (float*)d_out);
}

// round 16
// speedup vs baseline: 1.1211x; 1.0183x over previous
#include <cuda_runtime.h>
#include <cuda_fp16.h>
#include <math.h>
#include <cstdint>

#define NN 50000
#define EE 800000
#define BB 50
#define GN_EPS 1e-5f
#define MPAD 50048   // 391 * 128
#define SCAN_BLK 49  // ceil(NN / 1024)
#define GN_CHK 8

// ---------------- scratch (static device memory; no allocations) ----------------
__device__ float g_f0[(size_t)NN * 512];
__device__ float g_f1[(size_t)NN * 512];
__device__ __half g_abf[(size_t)MPAD * 1536];   // fp16 A; pad rows read-only garbage (discarded)
__device__ __half g_wbf[(size_t)512 * 2304];    // fp16 W (n-major)
__device__ __half g_cbf[(size_t)NN * 768];      // fp16 [P0|P1|P2] (mode B)
__device__ __half g_ubf[(size_t)NN * 256];      // fp16 u (mode B)
__device__ float g_s1p[GN_CHK * BB * 512];      // per-chunk partial sums
__device__ float g_s2p[GN_CHK * BB * 512];
__device__ float g_s1[BB * 512];                // final m / ww
__device__ float g_s2[BB * 512];
__device__ int   g_deg[NN];
__device__ int   g_off[NN + 1];
__device__ int   g_fill[NN];
__device__ int   g_bsum[SCAN_BLK];
__device__ int2  g_srcw[EE];   // {src, float_bits(w)}
__device__ int   g_ptr[BB + 1];
__device__ float g_pool[BB * 128];

static inline int cdiv(int a, int b) { return (a + b - 1) / b; }

// ---------------- PTX helpers ----------------
__device__ __forceinline__ uint32_t smem_u32(const void* p) {
    uint32_t a;
    asm("{ .reg .u64 t; cvta.to.shared.u64 t, %1; cvt.u32.u64 %0, t; }" : "=r"(a) : "l"(p));
    return a;
}

__device__ __forceinline__ void cp_async16(uint32_t dst, const void* src) {
    asm volatile("cp.async.cg.shared.global [%0], [%1], 16;\n" :: "r"(dst), "l"(src));
}
#define CP_COMMIT() asm volatile("cp.async.commit_group;\n" ::: "memory")
#define CP_WAIT(n)  asm volatile("cp.async.wait_group %0;\n" :: "n"(n) : "memory")

__device__ __forceinline__ void mma_f16(float* c, uint32_t a0, uint32_t a1, uint32_t a2,
                                        uint32_t a3, uint32_t b0, uint32_t b1) {
    asm volatile(
        "mma.sync.aligned.m16n8k16.row.col.f32.f16.f16.f32 "
        "{%0,%1,%2,%3}, {%4,%5,%6,%7}, {%8,%9}, {%0,%1,%2,%3};"
        : "+f"(c[0]), "+f"(c[1]), "+f"(c[2]), "+f"(c[3])
        : "r"(a0), "r"(a1), "r"(a2), "r"(a3), "r"(b0), "r"(b1));
}

__device__ __forceinline__ void ldsm_x4(uint32_t& r0, uint32_t& r1, uint32_t& r2,
                                        uint32_t& r3, uint32_t addr) {
    asm volatile("ldmatrix.sync.aligned.m8n8.x4.shared.b16 {%0,%1,%2,%3}, [%4];"
                 : "=r"(r0), "=r"(r1), "=r"(r2), "=r"(r3) : "r"(addr));
}

// fma of 8 fp16 channels (raw uint4) into 8 fp32 accumulators
__device__ __forceinline__ void fma8(float* acc, float w, const uint4& raw) {
    const __half2* hp = (const __half2*)&raw;
#pragma unroll
    for (int i = 0; i < 4; i++) {
        float2 v = __half22float2(hp[i]);
        acc[2 * i] = fmaf(w, v.x, acc[2 * i]);
        acc[2 * i + 1] = fmaf(w, v.y, acc[2 * i + 1]);
    }
}

// ---------------- setup kernels ----------------
__global__ void k_zero_deg() {
    int i = blockIdx.x * blockDim.x + threadIdx.x;
    if (i < NN) g_deg[i] = 0;
}

__global__ void k_deg(const int* __restrict__ dst) {
    int e = blockIdx.x * blockDim.x + threadIdx.x;
    if (e < EE) atomicAdd(&g_deg[dst[e]], 1);
}

// ---- 2-phase scan (scan2 folded into scan3) ----
__global__ void k_scan1() {
    __shared__ int red[256];
    int b = blockIdx.x;
    int t = threadIdx.x;
    int base = b * 1024 + t * 4;
    int s = 0;
#pragma unroll
    for (int i = 0; i < 4; i++) {
        int idx = base + i;
        if (idx < NN) s += g_deg[idx];
    }
    red[t] = s;
    __syncthreads();
    for (int off = 128; off > 0; off >>= 1) {
        if (t < off) red[t] += red[t + off];
        __syncthreads();
    }
    if (t == 0) g_bsum[b] = red[0];
}

__global__ void k_scan3() {
    __shared__ int pre[256];
    __shared__ int boff;
    int b = blockIdx.x;
    int t = threadIdx.x;
    if (t == 0) {
        int acc = 0;
        for (int i = 0; i < b; i++) acc += g_bsum[i];
        boff = acc;
        if (b == SCAN_BLK - 1) g_off[NN] = acc + g_bsum[b];
    }
    int base = b * 1024 + t * 4;
    int d[4];
    int s = 0;
#pragma unroll
    for (int i = 0; i < 4; i++) {
        int idx = base + i;
        d[i] = (idx < NN) ? g_deg[idx] : 0;
        s += d[i];
    }
    pre[t] = s;
    __syncthreads();
    for (int off = 1; off < 256; off <<= 1) {
        int v = (t >= off) ? pre[t - off] : 0;
        __syncthreads();
        pre[t] += v;
        __syncthreads();
    }
    int run = boff + pre[t] - s;
#pragma unroll
    for (int i = 0; i < 4; i++) {
        int idx = base + i;
        if (idx < NN) {
            g_off[idx] = run;
            g_fill[idx] = run;
            run += d[i];
        }
    }
}

// fill CSR; weight computed inline from degrees
__global__ void k_fill(const int* __restrict__ src, const int* __restrict__ dst) {
    int e = blockIdx.x * blockDim.x + threadIdx.x;
    if (e < EE) {
        int d = dst[e];
        int s = src[e];
        int pos = atomicAdd(&g_fill[d], 1);
        int ds = g_deg[s];
        int dd = g_deg[d];
        float w = (ds > 0) ? -rsqrtf((float)ds) * rsqrtf((float)dd) : 0.0f;
        g_srcw[pos] = make_int2(s, __float_as_int(w));
    }
}

__global__ void k_ptr(const int* __restrict__ batch) {
    int n = blockIdx.x * blockDim.x + threadIdx.x;
    if (n >= NN) return;
    int b = batch[n];
    if (n == 0) {
        for (int bb = 0; bb <= b; bb++) g_ptr[bb] = 0;
    } else {
        int pb = batch[n - 1];
        for (int bb = pb + 1; bb <= b; bb++) g_ptr[bb] = n;
    }
    if (n == NN - 1) {
        for (int bb = b + 1; bb <= BB; bb++) g_ptr[bb] = NN;
    }
}

// ---------------- propagation: 16B fp16 gathers, 8 channels/thread ----------------
template <int NCH, int NPB>
__global__ void __launch_bounds__((NCH / 8) * NPB) k_prop(
    const __half* __restrict__ hsrc, int hstr, int hoff,
    const __half* __restrict__ b1, int b1str, float c1,
    const __half* __restrict__ b2, int b2str, float c2,
    const float* __restrict__ bias, float scale,
    float* __restrict__ out, int ostr,
    __half* abf, int aoff, int astr) {
    int n = blockIdx.x * NPB + threadIdx.y;
    int c = threadIdx.x * 8;
    int s = g_off[n], e = g_off[n + 1];
    const __half* hb = hsrc + hoff + c;
    float a0[8] = {}, a1[8] = {};
    int ed = s;
    for (; ed + 4 <= e; ed += 4) {
        int2 p0 = g_srcw[ed], p1 = g_srcw[ed + 1], p2 = g_srcw[ed + 2], p3 = g_srcw[ed + 3];
        uint4 r0 = *(const uint4*)(hb + (size_t)p0.x * hstr);
        uint4 r1 = *(const uint4*)(hb + (size_t)p1.x * hstr);
        uint4 r2 = *(const uint4*)(hb + (size_t)p2.x * hstr);
        uint4 r3 = *(const uint4*)(hb + (size_t)p3.x * hstr);
        fma8(a0, __int_as_float(p0.y), r0);
        fma8(a1, __int_as_float(p1.y), r1);
        fma8(a0, __int_as_float(p2.y), r2);
        fma8(a1, __int_as_float(p3.y), r3);
    }
    for (; ed < e; ed++) {
        int2 p = g_srcw[ed];
        uint4 r = *(const uint4*)(hb + (size_t)p.x * hstr);
        fma8(a0, __int_as_float(p.y), r);
    }
    float r[8];
#pragma unroll
    for (int i = 0; i < 8; i++) r[i] = (a0[i] + a1[i]) * scale;
    if (b1) {
        uint4 raw = *(const uint4*)(b1 + (size_t)n * b1str + c);
        const __half2* hp = (const __half2*)&raw;
#pragma unroll
        for (int i = 0; i < 4; i++) {
            float2 v = __half22float2(hp[i]);
            r[2 * i] += c1 * v.x;
            r[2 * i + 1] += c1 * v.y;
        }
    }
    if (b2) {
        uint4 raw = *(const uint4*)(b2 + (size_t)n * b2str + c);
        const __half2* hp = (const __half2*)&raw;
#pragma unroll
        for (int i = 0; i < 4; i++) {
            float2 v = __half22float2(hp[i]);
            r[2 * i] += c2 * v.x;
            r[2 * i + 1] += c2 * v.y;
        }
    }
    if (bias) {
#pragma unroll
        for (int i = 0; i < 8; i++) r[i] += __ldg(bias + c + i);
    }
    if (out) {
        *(float4*)(out + (size_t)n * ostr + c) = make_float4(r[0], r[1], r[2], r[3]);
        *(float4*)(out + (size_t)n * ostr + c + 4) = make_float4(r[4], r[5], r[6], r[7]);
    }
    if (abf) {
        __half2 ov[4];
#pragma unroll
        for (int i = 0; i < 4; i++) ov[i] = __floats2half2_rn(r[2 * i], r[2 * i + 1]);
        *(uint4*)(abf + (size_t)n * astr + aoff + c) = *(uint4*)ov;
    }
}

// ---------------- fp16 convert of x ----------------
__global__ void k_convAx(const float* __restrict__ x) {
    int idx = blockIdx.x * blockDim.x + threadIdx.x;
    if (idx >= NN * 128) return;
    int n = idx >> 7;
    int c = idx & 127;
    g_abf[(size_t)n * 384 + c] = __float2half_rn(x[idx]);
}

// ---------------- weight converts ----------------
__global__ void k_convW(const float* __restrict__ W, int cin, int cout) {
    int K3 = 3 * cin;
    int idx = blockIdx.x * blockDim.x + threadIdx.x;
    if (idx >= cout * K3) return;
    int n = idx / K3;
    int R = idx - n * K3;
    g_wbf[(size_t)n * K3 + R] = __float2half_rn(W[(size_t)R * cout + n]);
}

__global__ void k_convWB(const float* __restrict__ W, int cin, int cout) {
    int idx = blockIdx.x * blockDim.x + threadIdx.x;
    if (idx >= 3 * cout * cin) return;
    int n = idx / cin;
    int k = idx - n * cin;
    int j = n / cout;
    int nc = n - j * cout;
    g_wbf[(size_t)n * cin + k] = __float2half_rn(W[((size_t)j * cin + k) * cout + nc]);
}

// ---------------- tensor-core GEMM: mma.sync + ldmatrix, 3-stage cp.async pipeline ----------------
#define BM 128
#define BN 128
#define BK 32
#define ASTR 40

__global__ void __launch_bounds__(256)
k_gemm_mma(const float* __restrict__ bias, float* __restrict__ C,
           __half* __restrict__ Ch, int K, int Ncols) {
    __shared__ __align__(16) __half As[3][BM * ASTR];
    __shared__ __align__(16) __half Bs[3][BN * ASTR];
    int tid = threadIdx.x;
    int lane = tid & 31;
    int wid = tid >> 5;
    int wm = wid >> 2;
    int wn = wid & 3;
    int m0 = blockIdx.x * BM;
    int n0 = blockIdx.y * BN;
    int nch = K / BK;

    float c[4][4][4] = {};

    int lrow = tid >> 2;
    int lcol = (tid & 3) * 8;
    uint32_t sa = smem_u32(As);
    uint32_t sb = smem_u32(Bs);
    uint32_t dstA = sa + (uint32_t)(lrow * ASTR + lcol) * 2;
    uint32_t dstB = sb + (uint32_t)(lrow * ASTR + lcol) * 2;
    const uint32_t bufsz = (uint32_t)BM * ASTR * 2;

    int qr = lane >> 2;
    int qc = (lane & 3) * 2;

    uint32_t a_off = (uint32_t)((wm * 64 + (lane & 15)) * ASTR + (lane >> 4) * 8) * 2;
    int bg_ = lane >> 3;
    uint32_t b_off = (uint32_t)((wn * 32 + (bg_ >> 1) * 8 + (lane & 7)) * ASTR
                                + (bg_ & 1) * 8) * 2;

    const __half* agb = g_abf + (size_t)(m0 + lrow) * K + lcol;
    const __half* bgb = g_wbf + (size_t)(n0 + lrow) * K + lcol;

#pragma unroll
    for (int pf = 0; pf < 2; pf++) {
        if (pf < nch) {
            int kg = pf * BK;
            uint32_t da = dstA + pf * bufsz;
            uint32_t db = dstB + pf * bufsz;
            cp_async16(da, agb + kg);
            cp_async16(da + 64u * ASTR * 2, agb + kg + (size_t)64 * K);
            cp_async16(db, bgb + kg);
            cp_async16(db + 64u * ASTR * 2, bgb + kg + (size_t)64 * K);
            CP_COMMIT();
        }
    }

    int buf = 0;
    for (int ch = 0; ch < nch; ch++) {
        if (ch + 2 < nch) {
            int kg = (ch + 2) * BK;
            int pbuf = (buf + 2 >= 3) ? buf - 1 : buf + 2;
            uint32_t da = dstA + pbuf * bufsz;
            uint32_t db = dstB + pbuf * bufsz;
            cp_async16(da, agb + kg);
            cp_async16(da + 64u * ASTR * 2, agb + kg + (size_t)64 * K);
            cp_async16(db, bgb + kg);
            cp_async16(db + 64u * ASTR * 2, bgb + kg + (size_t)64 * K);
            CP_COMMIT();
            CP_WAIT(2);
        } else if (ch + 1 < nch) {
            CP_WAIT(1);
        } else {
            CP_WAIT(0);
        }
        __syncthreads();

        uint32_t abase = sa + buf * bufsz + a_off;
        uint32_t bbase = sb + buf * bufsz + b_off;
#pragma unroll
        for (int ks = 0; ks < 2; ks++) {
            uint32_t kso = (uint32_t)(ks * 16) * 2;
            uint32_t a[4][4];
#pragma unroll
            for (int mi = 0; mi < 4; mi++)
                ldsm_x4(a[mi][0], a[mi][1], a[mi][2], a[mi][3],
                        abase + kso + (uint32_t)(mi * 16 * ASTR) * 2);
            uint32_t b[4][2];
#pragma unroll
            for (int nj = 0; nj < 2; nj++)
                ldsm_x4(b[nj * 2][0], b[nj * 2][1], b[nj * 2 + 1][0], b[nj * 2 + 1][1],
                        bbase + kso + (uint32_t)(nj * 16 * ASTR) * 2);
#pragma unroll
            for (int mi = 0; mi < 4; mi++)
#pragma unroll
                for (int ni = 0; ni < 4; ni++)
                    mma_f16(c[mi][ni], a[mi][0], a[mi][1], a[mi][2], a[mi][3],
                            b[ni][0], b[ni][1]);
        }
        __syncthreads();
        buf = (buf + 1 >= 3) ? 0 : buf + 1;
    }

    float bv0[4], bv1[4];
#pragma unroll
    for (int ni = 0; ni < 4; ni++) {
        int col = n0 + wn * 32 + ni * 8 + qc;
        bv0[ni] = bias ? bias[col] : 0.0f;
        bv1[ni] = bias ? bias[col + 1] : 0.0f;
    }
#pragma unroll
    for (int mi = 0; mi < 4; mi++) {
        int r = m0 + wm * 64 + mi * 16 + qr;
#pragma unroll
        for (int ni = 0; ni < 4; ni++) {
            int col = n0 + wn * 32 + ni * 8 + qc;
            if (r < NN) {
                float va = c[mi][ni][0] + bv0[ni];
                float vb = c[mi][ni][1] + bv1[ni];
                if (C) *(float2*)&C[(size_t)r * Ncols + col] = make_float2(va, vb);
                if (Ch) *(__half2*)&Ch[(size_t)r * Ncols + col] = __floats2half2_rn(va, vb);
            }
            if (r + 8 < NN) {
                float va = c[mi][ni][2] + bv0[ni];
                float vb = c[mi][ni][3] + bv1[ni];
                if (C) *(float2*)&C[(size_t)(r + 8) * Ncols + col] = make_float2(va, vb);
                if (Ch) *(__half2*)&Ch[(size_t)(r + 8) * Ncols + col] = __floats2half2_rn(va, vb);
            }
        }
    }
}

// ---------------- GraphNorm: atomic-free 3-phase ----------------
__global__ void k_gnstat(const float* __restrict__ X, int cout) {
    int bg = blockIdx.x;
    int c = blockIdx.y * 128 + threadIdx.x;
    int z = blockIdx.z;
    int s = g_ptr[bg], e = g_ptr[bg + 1];
    int len = e - s;
    int chunk = (len + GN_CHK - 1) / GN_CHK;
    int ns = s + z * chunk;
    int ne = min(ns + chunk, e);
    float s1 = 0.f, s2 = 0.f;
    for (int n = ns; n < ne; n++) {
        float v = X[(size_t)n * cout + c];
        s1 += v;
        s2 = fmaf(v, v, s2);
    }
    int o = (z * BB + bg) * cout + c;
    g_s1p[o] = s1;
    g_s2p[o] = s2;
}

__global__ void k_gnfin(const float* __restrict__ w, const float* __restrict__ ms,
                        int cout) {
    int idx = blockIdx.x * blockDim.x + threadIdx.x;
    if (idx >= BB * cout) return;
    int bg = idx / cout;
    int c = idx - bg * cout;
    float t1 = 0.f, t2 = 0.f;
#pragma unroll
    for (int z = 0; z < GN_CHK; z++) {
        t1 += g_s1p[(z * BB + bg) * cout + c];
        t2 += g_s2p[(z * BB + bg) * cout + c];
    }
    int cnt = g_ptr[bg + 1] - g_ptr[bg];
    float invc = 1.0f / (float)max(cnt, 1);
    float mean = t1 * invc;
    float m = ms[c] * mean;
    float var = fmaxf(t2 * invc - 2.0f * m * mean + m * m, 0.0f);
    g_s1[idx] = m;
    g_s2[idx] = w[c] * rsqrtf(var + GN_EPS);
}

// elementwise normalize + leaky relu -> fp16 (layers 1-3)
__global__ void k_gnnorm(const float* __restrict__ X, const float* __restrict__ b,
                         const int* __restrict__ batch, int cout, int lc,
                         __half* __restrict__ abf, int astr) {
    int idx = blockIdx.x * blockDim.x + threadIdx.x;
    int base = idx * 4;
    if (base >= NN * cout) return;
    int n = base >> lc;
    int c = base & (cout - 1);
    int bg = batch[n];
    float4 v = *(const float4*)(X + base);
    const float* s1 = g_s1 + bg * cout + c;
    const float* s2 = g_s2 + bg * cout + c;
    float r[4] = {v.x, v.y, v.z, v.w};
#pragma unroll
    for (int i = 0; i < 4; i++) {
        float t = s2[i] * (r[i] - s1[i]) + b[c + i];
        r[i] = (t >= 0.f) ? t : 0.2f * t;
    }
    __half2* ph = (__half2*)(abf + (size_t)n * astr + c);
    ph[0] = __floats2half2_rn(r[0], r[1]);
    ph[1] = __floats2half2_rn(r[2], r[3]);
}

// ---------------- fused layer-4 GN-normalize + residual + pool + MLP head ----------------
__global__ void __launch_bounds__(128)
k_poolhead(const float* __restrict__ h, const float* __restrict__ x,
           const float* __restrict__ gb,
           const float* __restrict__ W1, const float* __restrict__ b1,
           const float* __restrict__ W2, const float* __restrict__ b2,
           float* __restrict__ out) {
    __shared__ float pool[128];
    __shared__ float hid[64];
    int bg = blockIdx.x;
    int c = threadIdx.x;  // 128
    int s = g_ptr[bg];
    int e = g_ptr[bg + 1];
    float m = g_s1[bg * 128 + c];
    float ww = g_s2[bg * 128 + c];
    float bb = gb[c];
    float sum = 0.f;
    for (int n = s; n < e; n++) {
        float v = ww * (h[(size_t)n * 128 + c] - m) + bb;
        v = (v >= 0.f) ? v : 0.2f * v;
        sum += v + x[(size_t)n * 128 + c];
    }
    pool[c] = sum / (float)max(e - s, 1);
    __syncthreads();
    if (c < 64) {
        float acc = b1[c];
        for (int i = 0; i < 128; i++) acc += pool[i] * W1[i * 64 + c];
        hid[c] = tanhf(acc);
    }
    __syncthreads();
    if (c < 10) {
        float o = b2[c];
        for (int i = 0; i < 64; i++) o += hid[i] * W2[i * 10 + c];
        out[bg * 10 + c] = o;
    }
}

// ---------------- host orchestration ----------------
static void prop_launch(int nch, const __half* hsrc, int hstr, int hoff,
                        const __half* b1, int b1str, float c1,
                        const __half* b2, int b2str, float c2,
                        const float* bias, float scale,
                        float* out, int ostr,
                        __half* abf, int aoff, int astr) {
    if (nch == 128) {
        k_prop<128, 8><<<NN / 8, dim3(16, 8)>>>(hsrc, hstr, hoff, b1, b1str, c1,
                                                b2, b2str, c2, bias, scale,
                                                out, ostr, abf, aoff, astr);
    } else {
        k_prop<256, 4><<<NN / 4, dim3(32, 4)>>>(hsrc, hstr, hoff, b1, b1str, c1,
                                                b2, b2str, c2, bias, scale,
                                                out, ostr, abf, aoff, astr);
    }
}

static void gn_stats(const float* X, const float* w, const float* ms, int cout) {
    dim3 gs(BB, cout / 128, GN_CHK);
    k_gnstat<<<gs, 128>>>(X, cout);
    k_gnfin<<<cdiv(BB * cout, 256), 256>>>(w, ms, cout);
}

extern "C" void kernel_launch(void* const* d_in, const int* in_sizes, int n_in,
                              void* d_out, int out_size) {
    const float* x = (const float*)d_in[0];
    const int* ei = (const int*)d_in[1];
    const int* src = ei;
    const int* dst = ei + EE;
    const int* batch = (const int*)d_in[2];

    float *f0, *f1;
    __half *abf, *cbf, *ubf;
    cudaGetSymbolAddress((void**)&f0, g_f0);
    cudaGetSymbolAddress((void**)&f1, g_f1);
    cudaGetSymbolAddress((void**)&abf, g_abf);
    cudaGetSymbolAddress((void**)&cbf, g_cbf);
    cudaGetSymbolAddress((void**)&ubf, g_ubf);

    // ---- setup: degrees, CSR, graph segments ----
    k_zero_deg<<<cdiv(NN, 256), 256>>>();
    k_deg<<<cdiv(EE, 256), 256>>>(dst);
    k_scan1<<<SCAN_BLK, 256>>>();
    k_scan3<<<SCAN_BLK, 256>>>();
    k_fill<<<cdiv(EE, 256), 256>>>(src, dst);
    k_ptr<<<cdiv(NN, 256), 256>>>(batch);

    // ================= Layer 1 (mode A, 128 -> 256, K = 384) =================
    {
        const int cin = 128, cout = 256, K = 3 * cin;
        k_convAx<<<cdiv(NN * 128, 256), 256>>>(x);
        prop_launch(cin, abf, K, 0, nullptr, 0, 0.f, nullptr, 0, 0.f, nullptr, 1.0f,
                    nullptr, 0, abf, cin, K);
        prop_launch(cin, abf, K, cin, abf, K, -1.0f, nullptr, 0, 0.f, nullptr, 2.0f,
                    nullptr, 0, abf, 2 * cin, K);
        k_convW<<<cdiv(cout * K, 256), 256>>>((const float*)d_in[3], cin, cout);
        dim3 gg(MPAD / 128, cout / 128);
        k_gemm_mma<<<gg, 256>>>((const float*)d_in[4], f0, nullptr, K, cout);
        gn_stats(f0, (const float*)d_in[5], (const float*)d_in[7], cout);
        k_gnnorm<<<cdiv(NN * cout / 4, 256), 256>>>(f0, (const float*)d_in[6], batch,
                                                    cout, 8, abf, 3 * 256);
    }

    // ================= Layer 2 (mode A, 256 -> 512, K = 768) =================
    {
        const int cin = 256, cout = 512, K = 3 * cin;
        prop_launch(cin, abf, K, 0, nullptr, 0, 0.f, nullptr, 0, 0.f, nullptr, 1.0f,
                    nullptr, 0, abf, cin, K);
        prop_launch(cin, abf, K, cin, abf, K, -1.0f, nullptr, 0, 0.f, nullptr, 2.0f,
                    nullptr, 0, abf, 2 * cin, K);
        k_convW<<<cdiv(cout * K, 256), 256>>>((const float*)d_in[8], cin, cout);
        dim3 gg(MPAD / 128, cout / 128);
        k_gemm_mma<<<gg, 256>>>((const float*)d_in[9], f1, nullptr, K, cout);
        gn_stats(f1, (const float*)d_in[10], (const float*)d_in[12], cout);
        k_gnnorm<<<cdiv(NN * cout / 4, 256), 256>>>(f1, (const float*)d_in[11], batch,
                                                    cout, 9, abf, 512);
    }

    // ================= Layer 3 (mode B, 512 -> 256, K = 512) =================
    {
        const int cin = 512, cout = 256;
        k_convWB<<<cdiv(3 * cout * cin, 256), 256>>>((const float*)d_in[13], cin, cout);
        dim3 gg(MPAD / 128, (3 * cout) / 128);
        k_gemm_mma<<<gg, 256>>>(nullptr, nullptr, cbf, cin, 3 * cout);  // cbf=[P0|P1|P2] fp16
        prop_launch(cout, cbf, 3 * cout, 2 * cout, cbf + cout, 3 * cout, 1.0f,
                    nullptr, 0, 0.f, nullptr, 2.0f, nullptr, 0, ubf, 0, cout);
        prop_launch(cout, ubf, cout, 0, cbf, 3 * cout, 1.0f, cbf + 2 * cout, 3 * cout, -1.0f,
                    (const float*)d_in[14], 1.0f, f0, cout, nullptr, 0, 0);
        gn_stats(f0, (const float*)d_in[15], (const float*)d_in[17], cout);
        k_gnnorm<<<cdiv(NN * cout / 4, 256), 256>>>(f0, (const float*)d_in[16], batch,
                                                    cout, 8, abf, 256);
    }

    // ================= Layer 4 (mode B, 256 -> 128, K = 256) =================
    {
        const int cin = 256, cout = 128;
        k_convWB<<<cdiv(3 * cout * cin, 256), 256>>>((const float*)d_in[18], cin, cout);
        dim3 gg(MPAD / 128, (3 * cout) / 128);
        k_gemm_mma<<<gg, 256>>>(nullptr, nullptr, cbf, cin, 3 * cout);
        prop_launch(cout, cbf, 3 * cout, 2 * cout, cbf + cout, 3 * cout, 1.0f,
                    nullptr, 0, 0.f, nullptr, 2.0f, nullptr, 0, ubf, 0, cout);
        prop_launch(cout, ubf, cout, 0, cbf, 3 * cout, 1.0f, cbf + 2 * cout, 3 * cout, -1.0f,
                    (const float*)d_in[19], 1.0f, f1, cout, nullptr, 0, 0);
        gn_stats(f1, (const float*)d_in[20], (const float*)d_in[22], cout);
        // normalize + leaky + residual + pool + head, all fused
        k_poolhead<<<BB, 128>>>(f1, x, (const float*)d_in[21],
                                (const float*)d_in[23], (const float*)d_in[24],
                                (const float*)d_in[25], (const float*)d_in[26],
                                (float*)d_out);
    }
}

// round 17
// speedup vs baseline: 1.1735x; 1.0468x over previous
#include <cuda_runtime.h>
#include <cuda_fp16.h>
#include <math.h>
#include <cstdint>

#define NN 50000
#define EE 800000
#define BB 50
#define GN_EPS 1e-5f
#define MPAD 50048   // 391 * 128
#define SCAN_BLK 49  // ceil(NN / 1024)
#define GN_CHK 8

// ---------------- scratch (static device memory; no allocations) ----------------
__device__ float g_f0[(size_t)NN * 512];
__device__ float g_f1[(size_t)NN * 512];
__device__ __half g_abf[(size_t)MPAD * 1536];   // fp16 A; pad rows read-only garbage (discarded)
__device__ __half g_wbf[(size_t)512 * 2304];    // fp16 W (n-major)
__device__ __half g_cbf[(size_t)NN * 768];      // fp16 [P0|P1|P2] (mode B)
__device__ __half g_ubf[(size_t)NN * 256];      // fp16 u (mode B)
__device__ float g_s1p[GN_CHK * BB * 512];      // per-chunk partial sums
__device__ float g_s2p[GN_CHK * BB * 512];
__device__ float g_s1[BB * 512];                // final m / ww
__device__ float g_s2[BB * 512];
__device__ int   g_deg[NN];
__device__ int   g_off[NN + 1];
__device__ int   g_fill[NN];
__device__ int   g_bsum[SCAN_BLK];
__device__ int2  g_srcw[EE];   // {src, float_bits(w)}
__device__ int   g_ptr[BB + 1];

static inline int cdiv(int a, int b) { return (a + b - 1) / b; }

// ---------------- PTX helpers ----------------
__device__ __forceinline__ uint32_t smem_u32(const void* p) {
    uint32_t a;
    asm("{ .reg .u64 t; cvta.to.shared.u64 t, %1; cvt.u32.u64 %0, t; }" : "=r"(a) : "l"(p));
    return a;
}

__device__ __forceinline__ void cp_async16(uint32_t dst, const void* src) {
    asm volatile("cp.async.cg.shared.global [%0], [%1], 16;\n" :: "r"(dst), "l"(src));
}
#define CP_COMMIT() asm volatile("cp.async.commit_group;\n" ::: "memory")
#define CP_WAIT(n)  asm volatile("cp.async.wait_group %0;\n" :: "n"(n) : "memory")

__device__ __forceinline__ void mma_f16(float* c, uint32_t a0, uint32_t a1, uint32_t a2,
                                        uint32_t a3, uint32_t b0, uint32_t b1) {
    asm volatile(
        "mma.sync.aligned.m16n8k16.row.col.f32.f16.f16.f32 "
        "{%0,%1,%2,%3}, {%4,%5,%6,%7}, {%8,%9}, {%0,%1,%2,%3};"
        : "+f"(c[0]), "+f"(c[1]), "+f"(c[2]), "+f"(c[3])
        : "r"(a0), "r"(a1), "r"(a2), "r"(a3), "r"(b0), "r"(b1));
}

__device__ __forceinline__ void ldsm_x4(uint32_t& r0, uint32_t& r1, uint32_t& r2,
                                        uint32_t& r3, uint32_t addr) {
    asm volatile("ldmatrix.sync.aligned.m8n8.x4.shared.b16 {%0,%1,%2,%3}, [%4];"
                 : "=r"(r0), "=r"(r1), "=r"(r2), "=r"(r3) : "r"(addr));
}

// fma of 8 fp16 channels (raw uint4) into 8 fp32 accumulators
__device__ __forceinline__ void fma8(float* acc, float w, const uint4& raw) {
    const __half2* hp = (const __half2*)&raw;
#pragma unroll
    for (int i = 0; i < 4; i++) {
        float2 v = __half22float2(hp[i]);
        acc[2 * i] = fmaf(w, v.x, acc[2 * i]);
        acc[2 * i + 1] = fmaf(w, v.y, acc[2 * i + 1]);
    }
}

// ---------------- setup kernels ----------------
__global__ void k_zero_deg() {
    int i = blockIdx.x * blockDim.x + threadIdx.x;
    if (i < NN) g_deg[i] = 0;
}

__global__ void k_deg(const int* __restrict__ dst) {
    int e = blockIdx.x * blockDim.x + threadIdx.x;
    if (e < EE) atomicAdd(&g_deg[dst[e]], 1);
}

// ---- 2-phase scan ----
__global__ void k_scan1() {
    __shared__ int red[256];
    int b = blockIdx.x;
    int t = threadIdx.x;
    int base = b * 1024 + t * 4;
    int s = 0;
#pragma unroll
    for (int i = 0; i < 4; i++) {
        int idx = base + i;
        if (idx < NN) s += g_deg[idx];
    }
    red[t] = s;
    __syncthreads();
    for (int off = 128; off > 0; off >>= 1) {
        if (t < off) red[t] += red[t + off];
        __syncthreads();
    }
    if (t == 0) g_bsum[b] = red[0];
}

__global__ void k_scan3() {
    __shared__ int pre[256];
    __shared__ int boff;
    int b = blockIdx.x;
    int t = threadIdx.x;
    if (t == 0) {
        int acc = 0;
        for (int i = 0; i < b; i++) acc += g_bsum[i];
        boff = acc;
        if (b == SCAN_BLK - 1) g_off[NN] = acc + g_bsum[b];
    }
    int base = b * 1024 + t * 4;
    int d[4];
    int s = 0;
#pragma unroll
    for (int i = 0; i < 4; i++) {
        int idx = base + i;
        d[i] = (idx < NN) ? g_deg[idx] : 0;
        s += d[i];
    }
    pre[t] = s;
    __syncthreads();
    for (int off = 1; off < 256; off <<= 1) {
        int v = (t >= off) ? pre[t - off] : 0;
        __syncthreads();
        pre[t] += v;
        __syncthreads();
    }
    int run = boff + pre[t] - s;
#pragma unroll
    for (int i = 0; i < 4; i++) {
        int idx = base + i;
        if (idx < NN) {
            g_off[idx] = run;
            g_fill[idx] = run;
            run += d[i];
        }
    }
}

__global__ void k_fill(const int* __restrict__ src, const int* __restrict__ dst) {
    int e = blockIdx.x * blockDim.x + threadIdx.x;
    if (e < EE) {
        int d = dst[e];
        int s = src[e];
        int pos = atomicAdd(&g_fill[d], 1);
        int ds = g_deg[s];
        int dd = g_deg[d];
        float w = (ds > 0) ? -rsqrtf((float)ds) * rsqrtf((float)dd) : 0.0f;
        g_srcw[pos] = make_int2(s, __float_as_int(w));
    }
}

__global__ void k_ptr(const int* __restrict__ batch) {
    int n = blockIdx.x * blockDim.x + threadIdx.x;
    if (n >= NN) return;
    int b = batch[n];
    if (n == 0) {
        for (int bb = 0; bb <= b; bb++) g_ptr[bb] = 0;
    } else {
        int pb = batch[n - 1];
        for (int bb = pb + 1; bb <= b; bb++) g_ptr[bb] = n;
    }
    if (n == NN - 1) {
        for (int bb = b + 1; bb <= BB; bb++) g_ptr[bb] = NN;
    }
}

// ---------------- propagation: 16B fp16 gathers, 8 channels/thread ----------------
template <int NCH, int NPB>
__global__ void __launch_bounds__((NCH / 8) * NPB) k_prop(
    const __half* __restrict__ hsrc, int hstr, int hoff,
    const __half* __restrict__ b1, int b1str, float c1,
    const __half* __restrict__ b2, int b2str, float c2,
    const float* __restrict__ bias, float scale,
    float* __restrict__ out, int ostr,
    __half* abf, int aoff, int astr) {
    int n = blockIdx.x * NPB + threadIdx.y;
    int c = threadIdx.x * 8;
    int s = g_off[n], e = g_off[n + 1];
    const __half* hb = hsrc + hoff + c;
    float a0[8] = {}, a1[8] = {};
    int ed = s;
    for (; ed + 4 <= e; ed += 4) {
        int2 p0 = g_srcw[ed], p1 = g_srcw[ed + 1], p2 = g_srcw[ed + 2], p3 = g_srcw[ed + 3];
        uint4 r0 = *(const uint4*)(hb + (size_t)p0.x * hstr);
        uint4 r1 = *(const uint4*)(hb + (size_t)p1.x * hstr);
        uint4 r2 = *(const uint4*)(hb + (size_t)p2.x * hstr);
        uint4 r3 = *(const uint4*)(hb + (size_t)p3.x * hstr);
        fma8(a0, __int_as_float(p0.y), r0);
        fma8(a1, __int_as_float(p1.y), r1);
        fma8(a0, __int_as_float(p2.y), r2);
        fma8(a1, __int_as_float(p3.y), r3);
    }
    for (; ed < e; ed++) {
        int2 p = g_srcw[ed];
        uint4 r = *(const uint4*)(hb + (size_t)p.x * hstr);
        fma8(a0, __int_as_float(p.y), r);
    }
    float r[8];
#pragma unroll
    for (int i = 0; i < 8; i++) r[i] = (a0[i] + a1[i]) * scale;
    if (b1) {
        uint4 raw = *(const uint4*)(b1 + (size_t)n * b1str + c);
        const __half2* hp = (const __half2*)&raw;
#pragma unroll
        for (int i = 0; i < 4; i++) {
            float2 v = __half22float2(hp[i]);
            r[2 * i] += c1 * v.x;
            r[2 * i + 1] += c1 * v.y;
        }
    }
    if (b2) {
        uint4 raw = *(const uint4*)(b2 + (size_t)n * b2str + c);
        const __half2* hp = (const __half2*)&raw;
#pragma unroll
        for (int i = 0; i < 4; i++) {
            float2 v = __half22float2(hp[i]);
            r[2 * i] += c2 * v.x;
            r[2 * i + 1] += c2 * v.y;
        }
    }
    if (bias) {
#pragma unroll
        for (int i = 0; i < 8; i++) r[i] += __ldg(bias + c + i);
    }
    if (out) {
        *(float4*)(out + (size_t)n * ostr + c) = make_float4(r[0], r[1], r[2], r[3]);
        *(float4*)(out + (size_t)n * ostr + c + 4) = make_float4(r[4], r[5], r[6], r[7]);
    }
    if (abf) {
        __half2 ov[4];
#pragma unroll
        for (int i = 0; i < 4; i++) ov[i] = __floats2half2_rn(r[2 * i], r[2 * i + 1]);
        *(uint4*)(abf + (size_t)n * astr + aoff + c) = *(uint4*)ov;
    }
}

// ---------------- fp16 convert of x ----------------
__global__ void k_convAx(const float* __restrict__ x) {
    int idx = blockIdx.x * blockDim.x + threadIdx.x;
    if (idx >= NN * 128) return;
    int n = idx >> 7;
    int c = idx & 127;
    g_abf[(size_t)n * 384 + c] = __float2half_rn(x[idx]);
}

// ---------------- weight converts ----------------
__global__ void k_convW(const float* __restrict__ W, int cin, int cout) {
    int K3 = 3 * cin;
    int idx = blockIdx.x * blockDim.x + threadIdx.x;
    if (idx >= cout * K3) return;
    int n = idx / K3;
    int R = idx - n * K3;
    g_wbf[(size_t)n * K3 + R] = __float2half_rn(W[(size_t)R * cout + n]);
}

__global__ void k_convWB(const float* __restrict__ W, int cin, int cout) {
    int idx = blockIdx.x * blockDim.x + threadIdx.x;
    if (idx >= 3 * cout * cin) return;
    int n = idx / cin;
    int k = idx - n * cin;
    int j = n / cout;
    int nc = n - j * cout;
    g_wbf[(size_t)n * cin + k] = __float2half_rn(W[((size_t)j * cin + k) * cout + nc]);
}

// ---------------- tensor-core GEMM: 4-stage cp.async pipeline, ONE sync per chunk ----------------
#define BM 128
#define BN 128
#define BK 32
#define ASTR 40
#define STAGES 4

__global__ void __launch_bounds__(256)
k_gemm_mma(const float* __restrict__ bias, float* __restrict__ C,
           __half* __restrict__ Ch, int K, int Ncols) {
    __shared__ __align__(16) __half As[STAGES][BM * ASTR];
    __shared__ __align__(16) __half Bs[STAGES][BN * ASTR];
    int tid = threadIdx.x;
    int lane = tid & 31;
    int wid = tid >> 5;
    int wm = wid >> 2;
    int wn = wid & 3;
    int m0 = blockIdx.x * BM;
    int n0 = blockIdx.y * BN;
    int nch = K / BK;

    float c[4][4][4] = {};

    int lrow = tid >> 2;
    int lcol = (tid & 3) * 8;
    uint32_t sa = smem_u32(As);
    uint32_t sb = smem_u32(Bs);
    uint32_t dstA = sa + (uint32_t)(lrow * ASTR + lcol) * 2;
    uint32_t dstB = sb + (uint32_t)(lrow * ASTR + lcol) * 2;
    const uint32_t bufsz = (uint32_t)BM * ASTR * 2;

    int qr = lane >> 2;
    int qc = (lane & 3) * 2;

    uint32_t a_off = (uint32_t)((wm * 64 + (lane & 15)) * ASTR + (lane >> 4) * 8) * 2;
    int bg_ = lane >> 3;
    uint32_t b_off = (uint32_t)((wn * 32 + (bg_ >> 1) * 8 + (lane & 7)) * ASTR
                                + (bg_ & 1) * 8) * 2;

    const __half* agb = g_abf + (size_t)(m0 + lrow) * K + lcol;
    const __half* bgb = g_wbf + (size_t)(n0 + lrow) * K + lcol;

    // prologue: prefetch chunks 0..2 (each its own commit group; pad with empty groups)
#pragma unroll
    for (int pf = 0; pf < STAGES - 1; pf++) {
        if (pf < nch) {
            int kg = pf * BK;
            uint32_t da = dstA + pf * bufsz;
            uint32_t db = dstB + pf * bufsz;
            cp_async16(da, agb + kg);
            cp_async16(da + 64u * ASTR * 2, agb + kg + (size_t)64 * K);
            cp_async16(db, bgb + kg);
            cp_async16(db + 64u * ASTR * 2, bgb + kg + (size_t)64 * K);
        }
        CP_COMMIT();
    }

    int buf = 0;
    for (int ch = 0; ch < nch; ch++) {
        CP_WAIT(STAGES - 2);   // group for chunk `ch` complete
        __syncthreads();       // also: all warps done reading buffer (ch-1)%STAGES
        if (ch + STAGES - 1 < nch) {
            int kg = (ch + STAGES - 1) * BK;
            int pbuf = buf - 1;
            if (pbuf < 0) pbuf += STAGES;   // (ch+3)%4 == (ch-1)%4
            uint32_t da = dstA + pbuf * bufsz;
            uint32_t db = dstB + pbuf * bufsz;
            cp_async16(da, agb + kg);
            cp_async16(da + 64u * ASTR * 2, agb + kg + (size_t)64 * K);
            cp_async16(db, bgb + kg);
            cp_async16(db + 64u * ASTR * 2, bgb + kg + (size_t)64 * K);
        }
        CP_COMMIT();

        uint32_t abase = sa + buf * bufsz + a_off;
        uint32_t bbase = sb + buf * bufsz + b_off;
#pragma unroll
        for (int ks = 0; ks < 2; ks++) {
            uint32_t kso = (uint32_t)(ks * 16) * 2;
            uint32_t a[4][4];
#pragma unroll
            for (int mi = 0; mi < 4; mi++)
                ldsm_x4(a[mi][0], a[mi][1], a[mi][2], a[mi][3],
                        abase + kso + (uint32_t)(mi * 16 * ASTR) * 2);
            uint32_t b[4][2];
#pragma unroll
            for (int nj = 0; nj < 2; nj++)
                ldsm_x4(b[nj * 2][0], b[nj * 2][1], b[nj * 2 + 1][0], b[nj * 2 + 1][1],
                        bbase + kso + (uint32_t)(nj * 16 * ASTR) * 2);
#pragma unroll
            for (int mi = 0; mi < 4; mi++)
#pragma unroll
                for (int ni = 0; ni < 4; ni++)
                    mma_f16(c[mi][ni], a[mi][0], a[mi][1], a[mi][2], a[mi][3],
                            b[ni][0], b[ni][1]);
        }
        buf = (buf + 1 >= STAGES) ? 0 : buf + 1;
    }

    float bv0[4], bv1[4];
#pragma unroll
    for (int ni = 0; ni < 4; ni++) {
        int col = n0 + wn * 32 + ni * 8 + qc;
        bv0[ni] = bias ? bias[col] : 0.0f;
        bv1[ni] = bias ? bias[col + 1] : 0.0f;
    }
#pragma unroll
    for (int mi = 0; mi < 4; mi++) {
        int r = m0 + wm * 64 + mi * 16 + qr;
#pragma unroll
        for (int ni = 0; ni < 4; ni++) {
            int col = n0 + wn * 32 + ni * 8 + qc;
            if (r < NN) {
                float va = c[mi][ni][0] + bv0[ni];
                float vb = c[mi][ni][1] + bv1[ni];
                if (C) *(float2*)&C[(size_t)r * Ncols + col] = make_float2(va, vb);
                if (Ch) *(__half2*)&Ch[(size_t)r * Ncols + col] = __floats2half2_rn(va, vb);
            }
            if (r + 8 < NN) {
                float va = c[mi][ni][2] + bv0[ni];
                float vb = c[mi][ni][3] + bv1[ni];
                if (C) *(float2*)&C[(size_t)(r + 8) * Ncols + col] = make_float2(va, vb);
                if (Ch) *(__half2*)&Ch[(size_t)(r + 8) * Ncols + col] = __floats2half2_rn(va, vb);
            }
        }
    }
}

// ---------------- GraphNorm: atomic-free 3-phase ----------------
__global__ void k_gnstat(const float* __restrict__ X, int cout) {
    int bg = blockIdx.x;
    int c = blockIdx.y * 128 + threadIdx.x;
    int z = blockIdx.z;
    int s = g_ptr[bg], e = g_ptr[bg + 1];
    int len = e - s;
    int chunk = (len + GN_CHK - 1) / GN_CHK;
    int ns = s + z * chunk;
    int ne = min(ns + chunk, e);
    float s1 = 0.f, s2 = 0.f;
    for (int n = ns; n < ne; n++) {
        float v = X[(size_t)n * cout + c];
        s1 += v;
        s2 = fmaf(v, v, s2);
    }
    int o = (z * BB + bg) * cout + c;
    g_s1p[o] = s1;
    g_s2p[o] = s2;
}

__global__ void k_gnfin(const float* __restrict__ w, const float* __restrict__ ms,
                        int cout) {
    int idx = blockIdx.x * blockDim.x + threadIdx.x;
    if (idx >= BB * cout) return;
    int bg = idx / cout;
    int c = idx - bg * cout;
    float t1 = 0.f, t2 = 0.f;
#pragma unroll
    for (int z = 0; z < GN_CHK; z++) {
        t1 += g_s1p[(z * BB + bg) * cout + c];
        t2 += g_s2p[(z * BB + bg) * cout + c];
    }
    int cnt = g_ptr[bg + 1] - g_ptr[bg];
    float invc = 1.0f / (float)max(cnt, 1);
    float mean = t1 * invc;
    float m = ms[c] * mean;
    float var = fmaxf(t2 * invc - 2.0f * m * mean + m * m, 0.0f);
    g_s1[idx] = m;
    g_s2[idx] = w[c] * rsqrtf(var + GN_EPS);
}

// elementwise normalize + leaky relu -> fp16 (layers 1-3)
__global__ void k_gnnorm(const float* __restrict__ X, const float* __restrict__ b,
                         const int* __restrict__ batch, int cout, int lc,
                         __half* __restrict__ abf, int astr) {
    int idx = blockIdx.x * blockDim.x + threadIdx.x;
    int base = idx * 4;
    if (base >= NN * cout) return;
    int n = base >> lc;
    int c = base & (cout - 1);
    int bg = batch[n];
    float4 v = *(const float4*)(X + base);
    const float* s1 = g_s1 + bg * cout + c;
    const float* s2 = g_s2 + bg * cout + c;
    float r[4] = {v.x, v.y, v.z, v.w};
#pragma unroll
    for (int i = 0; i < 4; i++) {
        float t = s2[i] * (r[i] - s1[i]) + b[c + i];
        r[i] = (t >= 0.f) ? t : 0.2f * t;
    }
    __half2* ph = (__half2*)(abf + (size_t)n * astr + c);
    ph[0] = __floats2half2_rn(r[0], r[1]);
    ph[1] = __floats2half2_rn(r[2], r[3]);
}

// ---------------- fused layer-4 GN-normalize + residual + pool + MLP head ----------------
__global__ void __launch_bounds__(128)
k_poolhead(const float* __restrict__ h, const float* __restrict__ x,
           const float* __restrict__ gb,
           const float* __restrict__ W1, const float* __restrict__ b1,
           const float* __restrict__ W2, const float* __restrict__ b2,
           float* __restrict__ out) {
    __shared__ float pool[128];
    __shared__ float hid[64];
    int bg = blockIdx.x;
    int c = threadIdx.x;  // 128
    int s = g_ptr[bg];
    int e = g_ptr[bg + 1];
    float m = g_s1[bg * 128 + c];
    float ww = g_s2[bg * 128 + c];
    float bb = gb[c];
    float sum = 0.f;
    for (int n = s; n < e; n++) {
        float v = ww * (h[(size_t)n * 128 + c] - m) + bb;
        v = (v >= 0.f) ? v : 0.2f * v;
        sum += v + x[(size_t)n * 128 + c];
    }
    pool[c] = sum / (float)max(e - s, 1);
    __syncthreads();
    if (c < 64) {
        float acc = b1[c];
        for (int i = 0; i < 128; i++) acc += pool[i] * W1[i * 64 + c];
        hid[c] = tanhf(acc);
    }
    __syncthreads();
    if (c < 10) {
        float o = b2[c];
        for (int i = 0; i < 64; i++) o += hid[i] * W2[i * 10 + c];
        out[bg * 10 + c] = o;
    }
}

// ---------------- host orchestration ----------------
static void prop_launch(int nch, const __half* hsrc, int hstr, int hoff,
                        const __half* b1, int b1str, float c1,
                        const __half* b2, int b2str, float c2,
                        const float* bias, float scale,
                        float* out, int ostr,
                        __half* abf, int aoff, int astr) {
    if (nch == 128) {
        k_prop<128, 8><<<NN / 8, dim3(16, 8)>>>(hsrc, hstr, hoff, b1, b1str, c1,
                                                b2, b2str, c2, bias, scale,
                                                out, ostr, abf, aoff, astr);
    } else {
        k_prop<256, 4><<<NN / 4, dim3(32, 4)>>>(hsrc, hstr, hoff, b1, b1str, c1,
                                                b2, b2str, c2, bias, scale,
                                                out, ostr, abf, aoff, astr);
    }
}

static void gn_stats(const float* X, const float* w, const float* ms, int cout) {
    dim3 gs(BB, cout / 128, GN_CHK);
    k_gnstat<<<gs, 128>>>(X, cout);
    k_gnfin<<<cdiv(BB * cout, 256), 256>>>(w, ms, cout);
}

extern "C" void kernel_launch(void* const* d_in, const int* in_sizes, int n_in,
                              void* d_out, int out_size) {
    const float* x = (const float*)d_in[0];
    const int* ei = (const int*)d_in[1];
    const int* src = ei;
    const int* dst = ei + EE;
    const int* batch = (const int*)d_in[2];

    float *f0, *f1;
    __half *abf, *cbf, *ubf;
    cudaGetSymbolAddress((void**)&f0, g_f0);
    cudaGetSymbolAddress((void**)&f1, g_f1);
    cudaGetSymbolAddress((void**)&abf, g_abf);
    cudaGetSymbolAddress((void**)&cbf, g_cbf);
    cudaGetSymbolAddress((void**)&ubf, g_ubf);

    // ---- setup: degrees, CSR, graph segments ----
    k_zero_deg<<<cdiv(NN, 256), 256>>>();
    k_deg<<<cdiv(EE, 256), 256>>>(dst);
    k_scan1<<<SCAN_BLK, 256>>>();
    k_scan3<<<SCAN_BLK, 256>>>();
    k_fill<<<cdiv(EE, 256), 256>>>(src, dst);
    k_ptr<<<cdiv(NN, 256), 256>>>(batch);

    // ================= Layer 1 (mode A, 128 -> 256, K = 384) =================
    {
        const int cin = 128, cout = 256, K = 3 * cin;
        k_convAx<<<cdiv(NN * 128, 256), 256>>>(x);
        prop_launch(cin, abf, K, 0, nullptr, 0, 0.f, nullptr, 0, 0.f, nullptr, 1.0f,
                    nullptr, 0, abf, cin, K);
        prop_launch(cin, abf, K, cin, abf, K, -1.0f, nullptr, 0, 0.f, nullptr, 2.0f,
                    nullptr, 0, abf, 2 * cin, K);
        k_convW<<<cdiv(cout * K, 256), 256>>>((const float*)d_in[3], cin, cout);
        dim3 gg(MPAD / 128, cout / 128);
        k_gemm_mma<<<gg, 256>>>((const float*)d_in[4], f0, nullptr, K, cout);
        gn_stats(f0, (const float*)d_in[5], (const float*)d_in[7], cout);
        k_gnnorm<<<cdiv(NN * cout / 4, 256), 256>>>(f0, (const float*)d_in[6], batch,
                                                    cout, 8, abf, 3 * 256);
    }

    // ================= Layer 2 (mode A, 256 -> 512, K = 768) =================
    {
        const int cin = 256, cout = 512, K = 3 * cin;
        prop_launch(cin, abf, K, 0, nullptr, 0, 0.f, nullptr, 0, 0.f, nullptr, 1.0f,
                    nullptr, 0, abf, cin, K);
        prop_launch(cin, abf, K, cin, abf, K, -1.0f, nullptr, 0, 0.f, nullptr, 2.0f,
                    nullptr, 0, abf, 2 * cin, K);
        k_convW<<<cdiv(cout * K, 256), 256>>>((const float*)d_in[8], cin, cout);
        dim3 gg(MPAD / 128, cout / 128);
        k_gemm_mma<<<gg, 256>>>((const float*)d_in[9], f1, nullptr, K, cout);
        gn_stats(f1, (const float*)d_in[10], (const float*)d_in[12], cout);
        k_gnnorm<<<cdiv(NN * cout / 4, 256), 256>>>(f1, (const float*)d_in[11], batch,
                                                    cout, 9, abf, 512);
    }

    // ================= Layer 3 (mode B, 512 -> 256, K = 512) =================
    {
        const int cin = 512, cout = 256;
        k_convWB<<<cdiv(3 * cout * cin, 256), 256>>>((const float*)d_in[13], cin, cout);
        dim3 gg(MPAD / 128, (3 * cout) / 128);
        k_gemm_mma<<<gg, 256>>>(nullptr, nullptr, cbf, cin, 3 * cout);  // cbf=[P0|P1|P2] fp16
        prop_launch(cout, cbf, 3 * cout, 2 * cout, cbf + cout, 3 * cout, 1.0f,
                    nullptr, 0, 0.f, nullptr, 2.0f, nullptr, 0, ubf, 0, cout);
        prop_launch(cout, ubf, cout, 0, cbf, 3 * cout, 1.0f, cbf + 2 * cout, 3 * cout, -1.0f,
                    (const float*)d_in[14], 1.0f, f0, cout, nullptr, 0, 0);
        gn_stats(f0, (const float*)d_in[15], (const float*)d_in[17], cout);
        k_gnnorm<<<cdiv(NN * cout / 4, 256), 256>>>(f0, (const float*)d_in[16], batch,
                                                    cout, 8, abf, 256);
    }

    // ================= Layer 4 (mode B, 256 -> 128, K = 256) =================
    {
        const int cin = 256, cout = 128;
        k_convWB<<<cdiv(3 * cout * cin, 256), 256>>>((const float*)d_in[18], cin, cout);
        dim3 gg(MPAD / 128, (3 * cout) / 128);
        k_gemm_mma<<<gg, 256>>>(nullptr, nullptr, cbf, cin, 3 * cout);
        prop_launch(cout, cbf, 3 * cout, 2 * cout, cbf + cout, 3 * cout, 1.0f,
                    nullptr, 0, 0.f, nullptr, 2.0f, nullptr, 0, ubf, 0, cout);
        prop_launch(cout, ubf, cout, 0, cbf, 3 * cout, 1.0f, cbf + 2 * cout, 3 * cout, -1.0f,
                    (const float*)d_in[19], 1.0f, f1, cout, nullptr, 0, 0);
        gn_stats(f1, (const float*)d_in[20], (const float*)d_in[22], cout);
        k_poolhead<<<BB, 128>>>(f1, x, (const float*)d_in[21],
                                (const float*)d_in[23], (const float*)d_in[24],
                                (const float*)d_in[25], (const float*)d_in[26],
                                (float*)d_out);
    }
}